// round 1
// baseline (speedup 1.0000x reference)
#include <cuda_runtime.h>
#include <math.h>

#define BB 4
#define NN 4096
#define CC 1024
#define HH 8
#define DD 128
#define M_TOT (BB*NN)      // 16384
#define KV_CHUNKS 16
#define KM_CHUNKS 8

// ---------------- scratch (static device globals; no runtime allocation) ----------------
__device__ float g_qk[(size_t)M_TOT * 2 * CC];          // [16384, 2048]  q|k after elu+1
__device__ float g_qr[(size_t)M_TOT * CC];              // rope(q)
__device__ float g_kr[(size_t)M_TOT * CC];              // rope(k)
__device__ float g_kmean_part[KM_CHUNKS * BB * CC];
__device__ float g_kmean[BB * CC];
__device__ float g_z[BB * HH * NN];
__device__ float g_kv_part[(size_t)KV_CHUNKS * BB * HH * DD * DD];
__device__ float g_kv[(size_t)BB * HH * DD * DD];

// ---------------- GEMM 1: qk = elu(x @ qk_w + qk_b) + 1 ----------------
// A: [16384,1024] B: [1024,2048] C: [16384,2048]
__global__ void __launch_bounds__(256, 2)
gemm_qk_kernel(const float* __restrict__ A, const float* __restrict__ Bm,
               const float* __restrict__ bias)
{
    const int K = CC, Nd = 2 * CC;
    __shared__ float As[8 * 128];
    __shared__ float Bs[8 * 128];
    const int tid = threadIdx.x;
    const int br = blockIdx.y, bc = blockIdx.x;
    const float* Ablk = A + (size_t)br * 128 * K;
    const float* Bblk = Bm + bc * 128;
    float acc[8][8] = {};
    const int arow = tid >> 1, acol = (tid & 1) * 4;
    const int brow = tid >> 5, bcol = (tid & 31) * 4;
    const int trow = (tid >> 4) * 8, tcol = (tid & 15) * 8;
    for (int k0 = 0; k0 < K; k0 += 8) {
        float4 a4 = *(const float4*)(Ablk + (size_t)arow * K + k0 + acol);
        As[(acol + 0) * 128 + arow] = a4.x;
        As[(acol + 1) * 128 + arow] = a4.y;
        As[(acol + 2) * 128 + arow] = a4.z;
        As[(acol + 3) * 128 + arow] = a4.w;
        *(float4*)(Bs + brow * 128 + bcol) =
            *(const float4*)(Bblk + (size_t)(k0 + brow) * Nd + bcol);
        __syncthreads();
#pragma unroll
        for (int kk = 0; kk < 8; kk++) {
            float am[8], bn[8];
#pragma unroll
            for (int i = 0; i < 8; i++) am[i] = As[kk * 128 + trow + i];
#pragma unroll
            for (int j = 0; j < 8; j++) bn[j] = Bs[kk * 128 + tcol + j];
#pragma unroll
            for (int i = 0; i < 8; i++)
#pragma unroll
                for (int j = 0; j < 8; j++) acc[i][j] += am[i] * bn[j];
        }
        __syncthreads();
    }
#pragma unroll
    for (int i = 0; i < 8; i++) {
        const int gm = br * 128 + trow + i;
#pragma unroll
        for (int j = 0; j < 8; j++) {
            const int gc = bc * 128 + tcol + j;
            float v = acc[i][j] + bias[gc];
            v = (v > 0.0f) ? (v + 1.0f) : expf(v);   // elu(v)+1
            g_qk[(size_t)gm * Nd + gc] = v;
        }
    }
}

// ---------------- RoPE on q and k ----------------
__global__ void rope_kernel()
{
    const int idx = blockIdx.x * blockDim.x + threadIdx.x;   // m*512 + k
    if (idx >= M_TOT * 512) return;
    const int m = idx >> 9;
    const int k = idx & 511;
    const int n = m & (NN - 1);
    const float theta = (float)exp(-(double)k * (log(10000.0) / 512.0));
    const float ang = (float)n * theta;
    float s, c;
    sincosf(ang, &s, &c);
    const float* row = g_qk + (size_t)m * 2048;
    const float q0 = row[2 * k], q1 = row[2 * k + 1];
    g_qr[(size_t)m * 1024 + k]       = c * q0 - s * q1;
    g_qr[(size_t)m * 1024 + 512 + k] = c * q1 + s * q0;
    const float k0 = row[1024 + 2 * k], k1 = row[1024 + 2 * k + 1];
    g_kr[(size_t)m * 1024 + k]       = c * k0 - s * k1;
    g_kr[(size_t)m * 1024 + 512 + k] = c * k1 + s * k0;
}

// ---------------- k mean over n ----------------
__global__ void kmean_part_kernel()
{
    const int chunk = blockIdx.x;   // 0..7
    const int b = blockIdx.y;
    const int c4 = threadIdx.x * 4; // 256 threads * 4 = 1024 channels
    float4 s = make_float4(0.f, 0.f, 0.f, 0.f);
    for (int n = chunk * (NN / KM_CHUNKS); n < (chunk + 1) * (NN / KM_CHUNKS); n++) {
        const float4 v = *(const float4*)(g_qk + ((size_t)(b * NN + n)) * 2048 + 1024 + c4);
        s.x += v.x; s.y += v.y; s.z += v.z; s.w += v.w;
    }
    *(float4*)(&g_kmean_part[(chunk * BB + b) * CC + c4]) = s;
}

__global__ void kmean_fin_kernel()
{
    const int i = blockIdx.x * 256 + threadIdx.x;   // b*C + c, total 4096
    if (i >= BB * CC) return;
    float s = 0.f;
    for (int ch = 0; ch < KM_CHUNKS; ch++) s += g_kmean_part[ch * BB * CC + i];
    g_kmean[i] = s * (1.0f / NN);
}

// ---------------- z = 1 / (q . k_mean + 1e-6), one warp per (b,h,n) ----------------
__global__ void z_kernel()
{
    const int gw = (blockIdx.x * blockDim.x + threadIdx.x) >> 5;
    const int lane = threadIdx.x & 31;
    if (gw >= BB * HH * NN) return;
    const int n = gw & (NN - 1);
    const int h = (gw >> 12) & 7;
    const int b = gw >> 15;
    const float* qrow = g_qk + ((size_t)(b * NN + n)) * 2048 + h * 128;
    const float* km = g_kmean + b * CC + h * 128;
    const float4 qv = *(const float4*)(qrow + lane * 4);
    const float4 kv = *(const float4*)(km + lane * 4);
    float s = qv.x * kv.x + qv.y * kv.y + qv.z * kv.z + qv.w * kv.w;
#pragma unroll
    for (int o = 16; o; o >>= 1) s += __shfl_xor_sync(0xffffffffu, s, o);
    if (lane == 0) g_z[gw] = 1.0f / (s + 1e-6f);
}

// ---------------- kv partial: kv[d,e] = sum_n kr[n,d] * x[n,e], per (b,h,chunk) ----------------
__global__ void __launch_bounds__(256, 2)
kv_part_kernel(const float* __restrict__ x)
{
    const int chunk = blockIdx.x;       // 0..15
    const int bh = blockIdx.y;          // 0..31
    const int b = bh >> 3, h = bh & 7;
    const float* Abase = g_kr + ((size_t)b * NN) * CC + h * 128;
    const float* Bbase = x + ((size_t)b * NN) * CC + h * 128;
    __shared__ float As[8 * 128];
    __shared__ float Bs[8 * 128];
    float acc[8][8] = {};
    const int tid = threadIdx.x;
    const int lrow = tid >> 5, lcol = (tid & 31) * 4;
    const int trow = (tid >> 4) * 8, tcol = (tid & 15) * 8;
    const int n_beg = chunk * (NN / KV_CHUNKS);
    for (int n0 = n_beg; n0 < n_beg + NN / KV_CHUNKS; n0 += 8) {
        *(float4*)(As + lrow * 128 + lcol) =
            *(const float4*)(Abase + (size_t)(n0 + lrow) * CC + lcol);
        *(float4*)(Bs + lrow * 128 + lcol) =
            *(const float4*)(Bbase + (size_t)(n0 + lrow) * CC + lcol);
        __syncthreads();
#pragma unroll
        for (int kk = 0; kk < 8; kk++) {
            float am[8], bn[8];
#pragma unroll
            for (int i = 0; i < 8; i++) am[i] = As[kk * 128 + trow + i];
#pragma unroll
            for (int j = 0; j < 8; j++) bn[j] = Bs[kk * 128 + tcol + j];
#pragma unroll
            for (int i = 0; i < 8; i++)
#pragma unroll
                for (int j = 0; j < 8; j++) acc[i][j] += am[i] * bn[j];
        }
        __syncthreads();
    }
    float* out = g_kv_part + ((size_t)chunk * BB * HH + bh) * DD * DD;
#pragma unroll
    for (int i = 0; i < 8; i++)
#pragma unroll
        for (int j = 0; j < 8; j++)
            out[(trow + i) * 128 + tcol + j] = acc[i][j];
}

__global__ void kv_reduce_kernel()
{
    const int i = blockIdx.x * 256 + threadIdx.x;  // 32*16384
    if (i >= BB * HH * DD * DD) return;
    float s = 0.f;
    for (int ch = 0; ch < KV_CHUNKS; ch++)
        s += g_kv_part[(size_t)ch * BB * HH * DD * DD + i];
    g_kv[i] = s * (1.0f / 64.0f);   // 1/sqrt(4096)
}

// ---------------- out = (qr @ kv) * z, per (b,h) ----------------
__global__ void __launch_bounds__(256, 2)
out_kernel(float* __restrict__ out)
{
    const int rt = blockIdx.x;      // 0..31 (row tiles of n)
    const int bh = blockIdx.y;      // 0..31
    const int b = bh >> 3, h = bh & 7;
    const float* Abase = g_qr + ((size_t)b * NN) * CC + h * 128;   // [n,1024] strided
    const float* Bbase = g_kv + (size_t)bh * DD * DD;              // [128,128]
    __shared__ float As[8 * 128];
    __shared__ float Bs[8 * 128];
    float acc[8][8] = {};
    const int tid = threadIdx.x;
    const int arow = tid >> 1, acol = (tid & 1) * 4;
    const int brow = tid >> 5, bcol = (tid & 31) * 4;
    const int trow = (tid >> 4) * 8, tcol = (tid & 15) * 8;
    for (int k0 = 0; k0 < DD; k0 += 8) {
        float4 a4 = *(const float4*)(Abase + (size_t)(rt * 128 + arow) * CC + k0 + acol);
        As[(acol + 0) * 128 + arow] = a4.x;
        As[(acol + 1) * 128 + arow] = a4.y;
        As[(acol + 2) * 128 + arow] = a4.z;
        As[(acol + 3) * 128 + arow] = a4.w;
        *(float4*)(Bs + brow * 128 + bcol) =
            *(const float4*)(Bbase + (size_t)(k0 + brow) * DD + bcol);
        __syncthreads();
#pragma unroll
        for (int kk = 0; kk < 8; kk++) {
            float am[8], bn[8];
#pragma unroll
            for (int i = 0; i < 8; i++) am[i] = As[kk * 128 + trow + i];
#pragma unroll
            for (int j = 0; j < 8; j++) bn[j] = Bs[kk * 128 + tcol + j];
#pragma unroll
            for (int i = 0; i < 8; i++)
#pragma unroll
                for (int j = 0; j < 8; j++) acc[i][j] += am[i] * bn[j];
        }
        __syncthreads();
    }
#pragma unroll
    for (int i = 0; i < 8; i++) {
        const int n = rt * 128 + trow + i;
        const float zv = g_z[bh * NN + n];
#pragma unroll
        for (int j = 0; j < 8; j++) {
            out[((size_t)(b * NN + n)) * CC + h * 128 + tcol + j] = acc[i][j] * zv;
        }
    }
}

// ---------------- lepe conv (3 shifted GEMMs), accumulate into out ----------------
__global__ void __launch_bounds__(256, 2)
lepe_kernel(const float* __restrict__ x, const float* __restrict__ w,
            const float* __restrict__ bias, float* __restrict__ out)
{
    const int bc = blockIdx.x;      // 0..7  (col tiles)
    const int br = blockIdx.y;      // 0..127 (row tiles)
    __shared__ float As[8 * 128];
    __shared__ float Bs[8 * 128];
    float acc[8][8] = {};
    const int tid = threadIdx.x;
    const int arow = tid >> 1, acol = (tid & 1) * 4;
    const int brow = tid >> 5, bcol = (tid & 31) * 4;
    const int trow = (tid >> 4) * 8, tcol = (tid & 15) * 8;
    const int m0 = br * 128;

    for (int t = 0; t < 3; t++) {
        const float* wt = w + (size_t)t * CC * CC;
        const int m = m0 + arow;
        int n = (m & (NN - 1)) + t - 1;
        const int b = m >> 12;
        const bool valid = (n >= 0) && (n < NN);
        if (!valid) n = 0;
        const float* arow_ptr = x + ((size_t)(b * NN + n)) * CC;
        for (int k0 = 0; k0 < CC; k0 += 8) {
            float4 a4 = valid ? *(const float4*)(arow_ptr + k0 + acol)
                              : make_float4(0.f, 0.f, 0.f, 0.f);
            As[(acol + 0) * 128 + arow] = a4.x;
            As[(acol + 1) * 128 + arow] = a4.y;
            As[(acol + 2) * 128 + arow] = a4.z;
            As[(acol + 3) * 128 + arow] = a4.w;
            *(float4*)(Bs + brow * 128 + bcol) =
                *(const float4*)(wt + (size_t)(k0 + brow) * CC + bc * 128 + bcol);
            __syncthreads();
#pragma unroll
            for (int kk = 0; kk < 8; kk++) {
                float am[8], bn[8];
#pragma unroll
                for (int i = 0; i < 8; i++) am[i] = As[kk * 128 + trow + i];
#pragma unroll
                for (int j = 0; j < 8; j++) bn[j] = Bs[kk * 128 + tcol + j];
#pragma unroll
                for (int i = 0; i < 8; i++)
#pragma unroll
                    for (int j = 0; j < 8; j++) acc[i][j] += am[i] * bn[j];
            }
            __syncthreads();
        }
    }
#pragma unroll
    for (int i = 0; i < 8; i++) {
        const int gm = m0 + trow + i;
#pragma unroll
        for (int j = 0; j < 8; j++) {
            const int gc = bc * 128 + tcol + j;
            out[(size_t)gm * CC + gc] += acc[i][j] + bias[gc];
        }
    }
}

// ---------------- launch ----------------
extern "C" void kernel_launch(void* const* d_in, const int* in_sizes, int n_in,
                              void* d_out, int out_size)
{
    const float* x      = (const float*)d_in[0];
    const float* qk_w   = (const float*)d_in[1];
    const float* qk_b   = (const float*)d_in[2];
    const float* lepe_w = (const float*)d_in[3];
    const float* lepe_b = (const float*)d_in[4];
    float* out = (float*)d_out;

    gemm_qk_kernel<<<dim3(16, 128), 256>>>(x, qk_w, qk_b);
    rope_kernel<<<(M_TOT * 512) / 256, 256>>>();
    kmean_part_kernel<<<dim3(KM_CHUNKS, BB), 256>>>();
    kmean_fin_kernel<<<16, 256>>>();
    z_kernel<<<(BB * HH * NN * 32) / 256, 256>>>();
    kv_part_kernel<<<dim3(KV_CHUNKS, BB * HH), 256>>>(x);
    kv_reduce_kernel<<<(BB * HH * DD * DD) / 256, 256>>>();
    out_kernel<<<dim3(32, 32), 256>>>(out);
    lepe_kernel<<<dim3(8, 128), 256>>>(x, lepe_w, lepe_b, out);
}

// round 2
// speedup vs baseline: 2.4787x; 2.4787x over previous
#include <cuda_runtime.h>
#include <math.h>

#define BB 4
#define NN 4096
#define CC 1024
#define HH 8
#define DD 128
#define M_TOT (BB*NN)      // 16384
#define KV_CHUNKS 8
#define KM_CHUNKS 8

#define LDA_S 36
#define LDB_S 136

// ---------------- scratch ----------------
__device__ float g_qk[(size_t)M_TOT * 2 * CC];          // [16384, 2048]  q|k after elu+1
__device__ float g_qr[(size_t)M_TOT * CC];              // rope(q)
__device__ float g_kr[(size_t)M_TOT * CC];              // rope(k)
__device__ float g_kmean_part[KM_CHUNKS * BB * CC];
__device__ float g_kmean[BB * CC];
__device__ float g_z[BB * HH * NN];
__device__ float g_kv_part[(size_t)KV_CHUNKS * BB * HH * DD * DD];
__device__ float g_kv[(size_t)BB * HH * DD * DD];

// ---------------- tf32 helpers ----------------
__device__ __forceinline__ unsigned tf32_of(float f)
{
    unsigned u;
    asm("cvt.rna.tf32.f32 %0, %1;" : "=r"(u) : "f"(f));
    return u;
}

// fill As[m][k] (128x32, ld=36) from row-major A (row stride lda)
__device__ __forceinline__ void fill_A_rowmajor(unsigned* As, const float* A, size_t lda, int tid)
{
#pragma unroll
    for (int i = 0; i < 4; i++) {
        int idx = tid + i * 256;
        int r = idx >> 3;
        int c = (idx & 7) * 4;
        float4 v = *(const float4*)(A + (size_t)r * lda + c);
        unsigned* p = As + r * LDA_S + c;
        p[0] = tf32_of(v.x); p[1] = tf32_of(v.y); p[2] = tf32_of(v.z); p[3] = tf32_of(v.w);
    }
}

// fill As[m][k] from A stored [k][m] (32 rows x 128 cols, row stride lda) -- transposed
__device__ __forceinline__ void fill_A_trans(unsigned* As, const float* A, size_t lda, int tid)
{
#pragma unroll
    for (int i = 0; i < 4; i++) {
        int idx = tid + i * 256;
        int kr_ = idx >> 5;        // 0..31
        int c = (idx & 31) * 4;    // 0..124
        float4 v = *(const float4*)(A + (size_t)kr_ * lda + c);
        As[(c + 0) * LDA_S + kr_] = tf32_of(v.x);
        As[(c + 1) * LDA_S + kr_] = tf32_of(v.y);
        As[(c + 2) * LDA_S + kr_] = tf32_of(v.z);
        As[(c + 3) * LDA_S + kr_] = tf32_of(v.w);
    }
}

// fill Bs[k][n] (32x128, ld=136) from row-major B (row stride ldb)
__device__ __forceinline__ void fill_B(unsigned* Bs, const float* B, size_t ldb, int tid)
{
#pragma unroll
    for (int i = 0; i < 4; i++) {
        int idx = tid + i * 256;
        int r = idx >> 5;
        int c = (idx & 31) * 4;
        float4 v = *(const float4*)(B + (size_t)r * ldb + c);
        unsigned* p = Bs + r * LDB_S + c;
        p[0] = tf32_of(v.x); p[1] = tf32_of(v.y); p[2] = tf32_of(v.z); p[3] = tf32_of(v.w);
    }
}

// one 128x128x32 block-tile step; warp (wm,wn) computes 64x32 via 4x4 m16n8k8 tiles
__device__ __forceinline__ void mma_tile(const unsigned* As, const unsigned* Bs,
                                         int wm, int wn, int lane, float c[4][4][4])
{
    const int g = lane >> 2, t = lane & 3;
#pragma unroll
    for (int ks = 0; ks < 32; ks += 8) {
        unsigned a[4][4], b[4][2];
#pragma unroll
        for (int mt = 0; mt < 4; mt++) {
            const unsigned* p = As + (wm * 64 + mt * 16 + g) * LDA_S + ks + t;
            a[mt][0] = p[0];
            a[mt][1] = p[8 * LDA_S];
            a[mt][2] = p[4];
            a[mt][3] = p[8 * LDA_S + 4];
        }
#pragma unroll
        for (int nt = 0; nt < 4; nt++) {
            const unsigned* p = Bs + (ks + t) * LDB_S + wn * 32 + nt * 8 + g;
            b[nt][0] = p[0];
            b[nt][1] = p[4 * LDB_S];
        }
#pragma unroll
        for (int mt = 0; mt < 4; mt++)
#pragma unroll
            for (int nt = 0; nt < 4; nt++)
                asm volatile(
                    "mma.sync.aligned.m16n8k8.row.col.f32.tf32.tf32.f32 "
                    "{%0,%1,%2,%3},{%4,%5,%6,%7},{%8,%9},{%0,%1,%2,%3};"
                    : "+f"(c[mt][nt][0]), "+f"(c[mt][nt][1]),
                      "+f"(c[mt][nt][2]), "+f"(c[mt][nt][3])
                    : "r"(a[mt][0]), "r"(a[mt][1]), "r"(a[mt][2]), "r"(a[mt][3]),
                      "r"(b[nt][0]), "r"(b[nt][1]));
    }
}

// ---------------- GEMM 1: qk = elu(x @ qk_w + qk_b) + 1 ----------------
__global__ void __launch_bounds__(256)
gemm_qk_tc(const float* __restrict__ A, const float* __restrict__ Bm,
           const float* __restrict__ bias)
{
    __shared__ unsigned As[128 * LDA_S];
    __shared__ unsigned Bs[32 * LDB_S];
    const int tid = threadIdx.x, lane = tid & 31, wid = tid >> 5;
    const int wm = wid >> 2, wn = wid & 3;
    const int br = blockIdx.y, bc = blockIdx.x;
    float c[4][4][4] = {};
    const float* Ablk = A + (size_t)br * 128 * CC;
    const float* Bblk = Bm + bc * 128;
    for (int k0 = 0; k0 < CC; k0 += 32) {
        fill_A_rowmajor(As, Ablk + k0, CC, tid);
        fill_B(Bs, Bblk + (size_t)k0 * 2 * CC, 2 * CC, tid);
        __syncthreads();
        mma_tile(As, Bs, wm, wn, lane, c);
        __syncthreads();
    }
    const int g = lane >> 2, t = lane & 3;
#pragma unroll
    for (int mt = 0; mt < 4; mt++) {
#pragma unroll
        for (int nt = 0; nt < 4; nt++) {
            const int col = bc * 128 + wn * 32 + nt * 8 + 2 * t;
            const float b0 = bias[col], b1 = bias[col + 1];
#pragma unroll
            for (int e = 0; e < 2; e++) {
                const int row = br * 128 + wm * 64 + mt * 16 + g + e * 8;
                float v0 = c[mt][nt][2 * e]     + b0;
                float v1 = c[mt][nt][2 * e + 1] + b1;
                v0 = (v0 > 0.0f) ? (v0 + 1.0f) : expf(v0);
                v1 = (v1 > 0.0f) ? (v1 + 1.0f) : expf(v1);
                *(float2*)(g_qk + (size_t)row * 2048 + col) = make_float2(v0, v1);
            }
        }
    }
}

// ---------------- RoPE on q and k ----------------
__global__ void rope_kernel()
{
    const int idx = blockIdx.x * blockDim.x + threadIdx.x;
    if (idx >= M_TOT * 512) return;
    const int m = idx >> 9;
    const int k = idx & 511;
    const int n = m & (NN - 1);
    const float theta = (float)exp(-(double)k * (log(10000.0) / 512.0));
    const float ang = (float)n * theta;
    float s, cw;
    sincosf(ang, &s, &cw);
    const float* row = g_qk + (size_t)m * 2048;
    const float q0 = row[2 * k], q1 = row[2 * k + 1];
    g_qr[(size_t)m * 1024 + k]       = cw * q0 - s * q1;
    g_qr[(size_t)m * 1024 + 512 + k] = cw * q1 + s * q0;
    const float k0 = row[1024 + 2 * k], k1 = row[1024 + 2 * k + 1];
    g_kr[(size_t)m * 1024 + k]       = cw * k0 - s * k1;
    g_kr[(size_t)m * 1024 + 512 + k] = cw * k1 + s * k0;
}

// ---------------- k mean over n ----------------
__global__ void kmean_part_kernel()
{
    const int chunk = blockIdx.x;
    const int b = blockIdx.y;
    const int c4 = threadIdx.x * 4;
    float4 s = make_float4(0.f, 0.f, 0.f, 0.f);
    for (int n = chunk * (NN / KM_CHUNKS); n < (chunk + 1) * (NN / KM_CHUNKS); n++) {
        const float4 v = *(const float4*)(g_qk + ((size_t)(b * NN + n)) * 2048 + 1024 + c4);
        s.x += v.x; s.y += v.y; s.z += v.z; s.w += v.w;
    }
    *(float4*)(&g_kmean_part[(chunk * BB + b) * CC + c4]) = s;
}

__global__ void kmean_fin_kernel()
{
    const int i = blockIdx.x * 256 + threadIdx.x;
    if (i >= BB * CC) return;
    float s = 0.f;
    for (int ch = 0; ch < KM_CHUNKS; ch++) s += g_kmean_part[ch * BB * CC + i];
    g_kmean[i] = s * (1.0f / NN);
}

// ---------------- z = 1 / (q . k_mean + 1e-6) ----------------
__global__ void z_kernel()
{
    const int gw = (blockIdx.x * blockDim.x + threadIdx.x) >> 5;
    const int lane = threadIdx.x & 31;
    if (gw >= BB * HH * NN) return;
    const int n = gw & (NN - 1);
    const int h = (gw >> 12) & 7;
    const int b = gw >> 15;
    const float* qrow = g_qk + ((size_t)(b * NN + n)) * 2048 + h * 128;
    const float* km = g_kmean + b * CC + h * 128;
    const float4 qv = *(const float4*)(qrow + lane * 4);
    const float4 kv = *(const float4*)(km + lane * 4);
    float s = qv.x * kv.x + qv.y * kv.y + qv.z * kv.z + qv.w * kv.w;
#pragma unroll
    for (int o = 16; o; o >>= 1) s += __shfl_xor_sync(0xffffffffu, s, o);
    if (lane == 0) g_z[gw] = 1.0f / (s + 1e-6f);
}

// ---------------- kv partial: kv[d,e] = sum_n kr[n,d] * x[n,e] ----------------
__global__ void __launch_bounds__(256)
kv_tc(const float* __restrict__ x)
{
    __shared__ unsigned As[128 * LDA_S];
    __shared__ unsigned Bs[32 * LDB_S];
    const int tid = threadIdx.x, lane = tid & 31, wid = tid >> 5;
    const int wm = wid >> 2, wn = wid & 3;
    const int chunk = blockIdx.x;       // 0..KV_CHUNKS-1
    const int bh = blockIdx.y;          // 0..31
    const int b = bh >> 3, h = bh & 7;
    const float* Abase = g_kr + ((size_t)b * NN) * CC + h * 128;
    const float* Bbase = x + ((size_t)b * NN) * CC + h * 128;
    float c[4][4][4] = {};
    const int n_beg = chunk * (NN / KV_CHUNKS);
    for (int n0 = n_beg; n0 < n_beg + NN / KV_CHUNKS; n0 += 32) {
        fill_A_trans(As, Abase + (size_t)n0 * CC, CC, tid);
        fill_B(Bs, Bbase + (size_t)n0 * CC, CC, tid);
        __syncthreads();
        mma_tile(As, Bs, wm, wn, lane, c);
        __syncthreads();
    }
    float* out = g_kv_part + ((size_t)chunk * BB * HH + bh) * DD * DD;
    const int g = lane >> 2, t = lane & 3;
#pragma unroll
    for (int mt = 0; mt < 4; mt++)
#pragma unroll
        for (int nt = 0; nt < 4; nt++) {
            const int col = wn * 32 + nt * 8 + 2 * t;
#pragma unroll
            for (int e = 0; e < 2; e++) {
                const int row = wm * 64 + mt * 16 + g + e * 8;
                *(float2*)(out + row * DD + col) =
                    make_float2(c[mt][nt][2 * e], c[mt][nt][2 * e + 1]);
            }
        }
}

__global__ void kv_reduce_kernel()
{
    const int i = blockIdx.x * 256 + threadIdx.x;
    if (i >= BB * HH * DD * DD) return;
    float s = 0.f;
    for (int ch = 0; ch < KV_CHUNKS; ch++)
        s += g_kv_part[(size_t)ch * BB * HH * DD * DD + i];
    g_kv[i] = s * (1.0f / 64.0f);   // 1/sqrt(4096)
}

// ---------------- out = (qr @ kv) * z ----------------
__global__ void __launch_bounds__(256)
out_tc(float* __restrict__ out)
{
    __shared__ unsigned As[128 * LDA_S];
    __shared__ unsigned Bs[32 * LDB_S];
    const int tid = threadIdx.x, lane = tid & 31, wid = tid >> 5;
    const int wm = wid >> 2, wn = wid & 3;
    const int rt = blockIdx.x;      // n tile
    const int bh = blockIdx.y;
    const int b = bh >> 3, h = bh & 7;
    const float* Abase = g_qr + ((size_t)(b * NN + rt * 128)) * CC + h * 128;
    const float* Bbase = g_kv + (size_t)bh * DD * DD;
    float c[4][4][4] = {};
    for (int k0 = 0; k0 < DD; k0 += 32) {
        fill_A_rowmajor(As, Abase + k0, CC, tid);
        fill_B(Bs, Bbase + (size_t)k0 * DD, DD, tid);
        __syncthreads();
        mma_tile(As, Bs, wm, wn, lane, c);
        __syncthreads();
    }
    const int g = lane >> 2, t = lane & 3;
#pragma unroll
    for (int mt = 0; mt < 4; mt++)
#pragma unroll
        for (int e = 0; e < 2; e++) {
            const int n = rt * 128 + wm * 64 + mt * 16 + g + e * 8;
            const float zv = g_z[bh * NN + n];
            float* orow = out + ((size_t)(b * NN + n)) * CC + h * 128;
#pragma unroll
            for (int nt = 0; nt < 4; nt++) {
                const int col = wn * 32 + nt * 8 + 2 * t;
                *(float2*)(orow + col) =
                    make_float2(c[mt][nt][2 * e] * zv, c[mt][nt][2 * e + 1] * zv);
            }
        }
}

// ---------------- lepe conv (3 shifted GEMMs), accumulate into out ----------------
__global__ void __launch_bounds__(256)
lepe_tc(const float* __restrict__ x, const float* __restrict__ w,
        const float* __restrict__ bias, float* __restrict__ out)
{
    __shared__ unsigned As[128 * LDA_S];
    __shared__ unsigned Bs[32 * LDB_S];
    const int tid = threadIdx.x, lane = tid & 31, wid = tid >> 5;
    const int wm = wid >> 2, wn = wid & 3;
    const int bc = blockIdx.x;      // 0..7
    const int br = blockIdx.y;      // 0..127
    const int m0 = br * 128;
    float c[4][4][4] = {};

    for (int t3 = 0; t3 < 3; t3++) {
        const float* wt = w + (size_t)t3 * CC * CC + bc * 128;
        for (int k0 = 0; k0 < CC; k0 += 32) {
            // shifted A fill with zero padding
#pragma unroll
            for (int i = 0; i < 4; i++) {
                int idx = tid + i * 256;
                int r = idx >> 3;
                int col = (idx & 7) * 4;
                const int m = m0 + r;
                int n = (m & (NN - 1)) + t3 - 1;
                const int b = m >> 12;
                const bool valid = (n >= 0) && (n < NN);
                float4 v = valid ? *(const float4*)(x + ((size_t)(b * NN + n)) * CC + k0 + col)
                                 : make_float4(0.f, 0.f, 0.f, 0.f);
                unsigned* p = As + r * LDA_S + col;
                p[0] = tf32_of(v.x); p[1] = tf32_of(v.y);
                p[2] = tf32_of(v.z); p[3] = tf32_of(v.w);
            }
            fill_B(Bs, wt + (size_t)k0 * CC, CC, tid);
            __syncthreads();
            mma_tile(As, Bs, wm, wn, lane, c);
            __syncthreads();
        }
    }
    const int g = lane >> 2, t = lane & 3;
#pragma unroll
    for (int mt = 0; mt < 4; mt++)
#pragma unroll
        for (int nt = 0; nt < 4; nt++) {
            const int col = bc * 128 + wn * 32 + nt * 8 + 2 * t;
            const float b0 = bias[col], b1 = bias[col + 1];
#pragma unroll
            for (int e = 0; e < 2; e++) {
                const int row = m0 + wm * 64 + mt * 16 + g + e * 8;
                float* p = out + (size_t)row * CC + col;
                float2 old = *(float2*)p;
                *(float2*)p = make_float2(old.x + c[mt][nt][2 * e] + b0,
                                          old.y + c[mt][nt][2 * e + 1] + b1);
            }
        }
}

// ---------------- launch ----------------
extern "C" void kernel_launch(void* const* d_in, const int* in_sizes, int n_in,
                              void* d_out, int out_size)
{
    const float* x      = (const float*)d_in[0];
    const float* qk_w   = (const float*)d_in[1];
    const float* qk_b   = (const float*)d_in[2];
    const float* lepe_w = (const float*)d_in[3];
    const float* lepe_b = (const float*)d_in[4];
    float* out = (float*)d_out;

    gemm_qk_tc<<<dim3(16, 128), 256>>>(x, qk_w, qk_b);
    rope_kernel<<<(M_TOT * 512) / 256, 256>>>();
    kmean_part_kernel<<<dim3(KM_CHUNKS, BB), 256>>>();
    kmean_fin_kernel<<<16, 256>>>();
    z_kernel<<<(BB * HH * NN * 32) / 256, 256>>>();
    kv_tc<<<dim3(KV_CHUNKS, BB * HH), 256>>>(x);
    kv_reduce_kernel<<<(BB * HH * DD * DD) / 256, 256>>>();
    out_tc<<<dim3(32, 32), 256>>>(out);
    lepe_tc<<<dim3(8, 128), 256>>>(x, lepe_w, lepe_b, out);
}

// round 4
// speedup vs baseline: 4.1720x; 1.6831x over previous
#include <cuda_runtime.h>
#include <math.h>

#define BB 4
#define NN 4096
#define CC 1024
#define HH 8
#define DD 128
#define M_TOT (BB*NN)      // 16384
#define KV_CHUNKS 8
#define KM_CHUNKS 8

#define LDA_S 36
#define LDB_S 136

// pipelined GEMM smem geometry (bytes)
#define A_STAGE_B (128 * 144)      // 128 rows x 36 floats
#define B_STAGE_B (32 * 544)       // 32 rows x 136 floats
#define STAGE_B   (A_STAGE_B + B_STAGE_B)   // 35840
#define NSTAGE    3
#define DSMEM_BYTES (NSTAGE * STAGE_B)      // 107520

// ---------------- scratch ----------------
__device__ float g_qk[(size_t)M_TOT * 2 * CC];
__device__ float g_qr[(size_t)M_TOT * CC];
__device__ float g_kr[(size_t)M_TOT * CC];
__device__ float g_kmean_part[KM_CHUNKS * BB * CC];
__device__ float g_kmean[BB * CC];
__device__ float g_z[BB * HH * NN];
__device__ float g_kv_part[(size_t)KV_CHUNKS * BB * HH * DD * DD];
__device__ float g_kv[(size_t)BB * HH * DD * DD];
__device__ float g_xt[(size_t)M_TOT * CC];           // tf32-rounded x
__device__ float g_qkwC[(size_t)CC * 2 * CC];        // tf32-rounded qk_w [1024][2048]
__device__ float g_lepewC[(size_t)3 * CC * CC];      // tf32-rounded lepe_w

// ---------------- helpers ----------------
__device__ __forceinline__ unsigned tf32_of(float f)
{
    unsigned u;
    asm("cvt.rna.tf32.f32 %0, %1;" : "=r"(u) : "f"(f));
    return u;
}
__device__ __forceinline__ float tf32f(float f) { return __uint_as_float(tf32_of(f)); }
__device__ __forceinline__ unsigned sptr(const void* p)
{
    return (unsigned)__cvta_generic_to_shared(p);
}
__device__ __forceinline__ void cp16(unsigned dst, const void* src)
{
    asm volatile("cp.async.cg.shared.global [%0], [%1], 16;" :: "r"(dst), "l"(src));
}
__device__ __forceinline__ void cp16z(unsigned dst, const void* src, int sz)
{
    asm volatile("cp.async.cg.shared.global [%0], [%1], 16, %2;" :: "r"(dst), "l"(src), "r"(sz));
}
#define CP_COMMIT() asm volatile("cp.async.commit_group;" ::: "memory")
#define CP_WAIT1()  asm volatile("cp.async.wait_group 1;" ::: "memory")
#define CP_WAIT0()  asm volatile("cp.async.wait_group 0;" ::: "memory")

// ---------------- tf32 conversion prepass ----------------
__global__ void cvt_tf32_kernel(const float* __restrict__ src, float* __restrict__ dst)
{
    const size_t i = ((size_t)blockIdx.x * blockDim.x + threadIdx.x) * 4;
    float4 v = *(const float4*)(src + i);
    *(float4*)(dst + i) = make_float4(tf32f(v.x), tf32f(v.y), tf32f(v.z), tf32f(v.w));
}

// ---------------- warp-tile MMA on staged smem (As ld=36, Bs ld=136) ----------------
__device__ __forceinline__ void mma_tile(const unsigned* As, const unsigned* Bs,
                                         int wm, int wn, int lane, float c[4][4][4])
{
    const int g = lane >> 2, t = lane & 3;
#pragma unroll
    for (int ks = 0; ks < 32; ks += 8) {
        unsigned a[4][4], b[4][2];
#pragma unroll
        for (int mt = 0; mt < 4; mt++) {
            const unsigned* p = As + (wm * 64 + mt * 16 + g) * LDA_S + ks + t;
            a[mt][0] = p[0];
            a[mt][1] = p[8 * LDA_S];
            a[mt][2] = p[4];
            a[mt][3] = p[8 * LDA_S + 4];
        }
#pragma unroll
        for (int nt = 0; nt < 4; nt++) {
            const unsigned* p = Bs + (ks + t) * LDB_S + wn * 32 + nt * 8 + g;
            b[nt][0] = p[0];
            b[nt][1] = p[4 * LDB_S];
        }
#pragma unroll
        for (int mt = 0; mt < 4; mt++)
#pragma unroll
            for (int nt = 0; nt < 4; nt++)
                asm volatile(
                    "mma.sync.aligned.m16n8k8.row.col.f32.tf32.tf32.f32 "
                    "{%0,%1,%2,%3},{%4,%5,%6,%7},{%8,%9},{%0,%1,%2,%3};"
                    : "+f"(c[mt][nt][0]), "+f"(c[mt][nt][1]),
                      "+f"(c[mt][nt][2]), "+f"(c[mt][nt][3])
                    : "r"(a[mt][0]), "r"(a[mt][1]), "r"(a[mt][2]), "r"(a[mt][3]),
                      "r"(b[nt][0]), "r"(b[nt][1]));
    }
}

// ---------------- qk GEMM: cp.async 3-stage pipeline ----------------
__global__ void __launch_bounds__(256, 2)
gemm_qk_cp(const float* __restrict__ bias)
{
    extern __shared__ __align__(16) char dsm[];
    const unsigned base = sptr(dsm);
    const int tid = threadIdx.x, lane = tid & 31, wid = tid >> 5;
    const int wm = wid >> 2, wn = wid & 3;
    const int br = blockIdx.y, bc = blockIdx.x;
    const float* Ab = g_xt + (size_t)br * 128 * CC;
    const float* Bw = g_qkwC + bc * 128;

    const int ar = tid >> 3, ac = tid & 7;       // A: 4 chunks/thread
    const int brw = tid >> 5, bcw = tid & 31;    // B: 4 chunks/thread

    auto fill = [&](int kt, int st) {
        const int k0 = kt * 32;
        const unsigned Abase = base + st * STAGE_B;
        const unsigned Bbase = Abase + A_STAGE_B;
#pragma unroll
        for (int i = 0; i < 4; i++) {
            const int r = ar + i * 32;
            cp16(Abase + r * 144 + ac * 16, Ab + (size_t)r * CC + k0 + ac * 4);
        }
#pragma unroll
        for (int i = 0; i < 4; i++) {
            const int r = brw + i * 8;
            cp16(Bbase + r * 544 + bcw * 16, Bw + (size_t)(k0 + r) * 2048 + bcw * 4);
        }
    };

    float c[4][4][4] = {};
    fill(0, 0); CP_COMMIT();
    fill(1, 1); CP_COMMIT();
    for (int kt = 0; kt < 32; kt++) {
        const int st = kt % NSTAGE;
        CP_WAIT1();
        __syncthreads();
        if (kt + 2 < 32) fill(kt + 2, (kt + 2) % NSTAGE);
        CP_COMMIT();
        const unsigned* As = (const unsigned*)(dsm + st * STAGE_B);
        const unsigned* Bs = (const unsigned*)(dsm + st * STAGE_B + A_STAGE_B);
        mma_tile(As, Bs, wm, wn, lane, c);
        __syncthreads();
    }

    const int g = lane >> 2, t = lane & 3;
#pragma unroll
    for (int mt = 0; mt < 4; mt++) {
#pragma unroll
        for (int nt = 0; nt < 4; nt++) {
            const int col = bc * 128 + wn * 32 + nt * 8 + 2 * t;
            const float b0 = bias[col], b1 = bias[col + 1];
#pragma unroll
            for (int e = 0; e < 2; e++) {
                const int row = br * 128 + wm * 64 + mt * 16 + g + e * 8;
                float v0 = c[mt][nt][2 * e]     + b0;
                float v1 = c[mt][nt][2 * e + 1] + b1;
                v0 = (v0 > 0.0f) ? (v0 + 1.0f) : expf(v0);
                v1 = (v1 > 0.0f) ? (v1 + 1.0f) : expf(v1);
                *(float2*)(g_qk + (size_t)row * 2048 + col) = make_float2(v0, v1);
            }
        }
    }
}

// ---------------- lepe conv GEMM: 3 taps x 32 k-tiles, cp.async pipeline ----------------
__global__ void __launch_bounds__(256, 2)
lepe_cp(const float* __restrict__ bias, float* __restrict__ out)
{
    extern __shared__ __align__(16) char dsm[];
    const unsigned base = sptr(dsm);
    const int tid = threadIdx.x, lane = tid & 31, wid = tid >> 5;
    const int wm = wid >> 2, wn = wid & 3;
    const int br = blockIdx.y, bc = blockIdx.x;
    const int m0 = br * 128;

    const int ar = tid >> 3, ac = tid & 7;
    const int brw = tid >> 5, bcw = tid & 31;

    auto fill = [&](int kt, int st) {
        const int tap = kt >> 5;
        const int k0 = (kt & 31) * 32;
        const float* Bw = g_lepewC + (size_t)tap * CC * CC + bc * 128;
        const unsigned Abase = base + st * STAGE_B;
        const unsigned Bbase = Abase + A_STAGE_B;
#pragma unroll
        for (int i = 0; i < 4; i++) {
            const int r = ar + i * 32;
            const int m = m0 + r;
            int n = (m & (NN - 1)) + tap - 1;
            const int b = m >> 12;
            const bool valid = (n >= 0) && (n < NN);
            if (!valid) n = 0;
            cp16z(Abase + r * 144 + ac * 16,
                  g_xt + ((size_t)(b * NN + n)) * CC + k0 + ac * 4, valid ? 16 : 0);
        }
#pragma unroll
        for (int i = 0; i < 4; i++) {
            const int r = brw + i * 8;
            cp16(Bbase + r * 544 + bcw * 16, Bw + (size_t)(k0 + r) * CC + bcw * 4);
        }
    };

    float c[4][4][4] = {};
    fill(0, 0); CP_COMMIT();
    fill(1, 1); CP_COMMIT();
    for (int kt = 0; kt < 96; kt++) {
        const int st = kt % NSTAGE;
        CP_WAIT1();
        __syncthreads();
        if (kt + 2 < 96) fill(kt + 2, (kt + 2) % NSTAGE);
        CP_COMMIT();
        const unsigned* As = (const unsigned*)(dsm + st * STAGE_B);
        const unsigned* Bs = (const unsigned*)(dsm + st * STAGE_B + A_STAGE_B);
        mma_tile(As, Bs, wm, wn, lane, c);
        __syncthreads();
    }

    const int g = lane >> 2, t = lane & 3;
#pragma unroll
    for (int mt = 0; mt < 4; mt++)
#pragma unroll
        for (int nt = 0; nt < 4; nt++) {
            const int col = bc * 128 + wn * 32 + nt * 8 + 2 * t;
            const float b0 = bias[col], b1 = bias[col + 1];
#pragma unroll
            for (int e = 0; e < 2; e++) {
                const int row = m0 + wm * 64 + mt * 16 + g + e * 8;
                float* p = out + (size_t)row * CC + col;
                float2 old = *(float2*)p;
                *(float2*)p = make_float2(old.x + c[mt][nt][2 * e] + b0,
                                          old.y + c[mt][nt][2 * e + 1] + b1);
            }
        }
}

// ---------------- RoPE (outputs tf32-rounded) ----------------
__global__ void rope_kernel()
{
    const int idx = blockIdx.x * blockDim.x + threadIdx.x;
    if (idx >= M_TOT * 512) return;
    const int m = idx >> 9;
    const int k = idx & 511;
    const int n = m & (NN - 1);
    const float theta = (float)exp(-(double)k * (log(10000.0) / 512.0));
    const float ang = (float)n * theta;
    float s, cw;
    sincosf(ang, &s, &cw);
    const float* row = g_qk + (size_t)m * 2048;
    const float q0 = row[2 * k], q1 = row[2 * k + 1];
    g_qr[(size_t)m * 1024 + k]       = tf32f(cw * q0 - s * q1);
    g_qr[(size_t)m * 1024 + 512 + k] = tf32f(cw * q1 + s * q0);
    const float k0 = row[1024 + 2 * k], k1 = row[1024 + 2 * k + 1];
    g_kr[(size_t)m * 1024 + k]       = tf32f(cw * k0 - s * k1);
    g_kr[(size_t)m * 1024 + 512 + k] = tf32f(cw * k1 + s * k0);
}

// ---------------- k mean ----------------
__global__ void kmean_part_kernel()
{
    const int chunk = blockIdx.x;
    const int b = blockIdx.y;
    const int c4 = threadIdx.x * 4;
    float4 s = make_float4(0.f, 0.f, 0.f, 0.f);
    for (int n = chunk * (NN / KM_CHUNKS); n < (chunk + 1) * (NN / KM_CHUNKS); n++) {
        const float4 v = *(const float4*)(g_qk + ((size_t)(b * NN + n)) * 2048 + 1024 + c4);
        s.x += v.x; s.y += v.y; s.z += v.z; s.w += v.w;
    }
    *(float4*)(&g_kmean_part[(chunk * BB + b) * CC + c4]) = s;
}

__global__ void kmean_fin_kernel()
{
    const int i = blockIdx.x * 256 + threadIdx.x;
    if (i >= BB * CC) return;
    float s = 0.f;
    for (int ch = 0; ch < KM_CHUNKS; ch++) s += g_kmean_part[ch * BB * CC + i];
    g_kmean[i] = s * (1.0f / NN);
}

// ---------------- z = 1 / (q . k_mean + 1e-6) ----------------
__global__ void z_kernel()
{
    const int gw = (blockIdx.x * blockDim.x + threadIdx.x) >> 5;
    const int lane = threadIdx.x & 31;
    if (gw >= BB * HH * NN) return;
    const int n = gw & (NN - 1);
    const int h = (gw >> 12) & 7;
    const int b = gw >> 15;
    const float* qrow = g_qk + ((size_t)(b * NN + n)) * 2048 + h * 128;
    const float* km = g_kmean + b * CC + h * 128;
    const float4 qv = *(const float4*)(qrow + lane * 4);
    const float4 kv = *(const float4*)(km + lane * 4);
    float s = qv.x * kv.x + qv.y * kv.y + qv.z * kv.z + qv.w * kv.w;
#pragma unroll
    for (int o = 16; o; o >>= 1) s += __shfl_xor_sync(0xffffffffu, s, o);
    if (lane == 0) g_z[gw] = 1.0f / (s + 1e-6f);
}

// ---------------- kv / out (R2-style single-buffer tiles) ----------------
__device__ __forceinline__ void fill_A_rowmajor(unsigned* As, const float* A, size_t lda, int tid)
{
#pragma unroll
    for (int i = 0; i < 4; i++) {
        int idx = tid + i * 256;
        int r = idx >> 3;
        int c = (idx & 7) * 4;
        float4 v = *(const float4*)(A + (size_t)r * lda + c);
        unsigned* p = As + r * LDA_S + c;
        p[0] = __float_as_uint(v.x); p[1] = __float_as_uint(v.y);
        p[2] = __float_as_uint(v.z); p[3] = __float_as_uint(v.w);
    }
}
__device__ __forceinline__ void fill_A_trans(unsigned* As, const float* A, size_t lda, int tid)
{
#pragma unroll
    for (int i = 0; i < 4; i++) {
        int idx = tid + i * 256;
        int kr_ = idx >> 5;
        int c = (idx & 31) * 4;
        float4 v = *(const float4*)(A + (size_t)kr_ * lda + c);
        As[(c + 0) * LDA_S + kr_] = __float_as_uint(v.x);
        As[(c + 1) * LDA_S + kr_] = __float_as_uint(v.y);
        As[(c + 2) * LDA_S + kr_] = __float_as_uint(v.z);
        As[(c + 3) * LDA_S + kr_] = __float_as_uint(v.w);
    }
}
__device__ __forceinline__ void fill_B(unsigned* Bs, const float* B, size_t ldb, int tid)
{
#pragma unroll
    for (int i = 0; i < 4; i++) {
        int idx = tid + i * 256;
        int r = idx >> 5;
        int c = (idx & 31) * 4;
        float4 v = *(const float4*)(B + (size_t)r * ldb + c);
        unsigned* p = Bs + r * LDB_S + c;
        p[0] = __float_as_uint(v.x); p[1] = __float_as_uint(v.y);
        p[2] = __float_as_uint(v.z); p[3] = __float_as_uint(v.w);
    }
}

__global__ void __launch_bounds__(256)
kv_tc()
{
    __shared__ unsigned As[128 * LDA_S];
    __shared__ unsigned Bs[32 * LDB_S];
    const int tid = threadIdx.x, lane = tid & 31, wid = tid >> 5;
    const int wm = wid >> 2, wn = wid & 3;
    const int chunk = blockIdx.x;
    const int bh = blockIdx.y;
    const int b = bh >> 3, h = bh & 7;
    const float* Abase = g_kr + ((size_t)b * NN) * CC + h * 128;
    const float* Bbase = g_xt + ((size_t)b * NN) * CC + h * 128;
    float c[4][4][4] = {};
    const int n_beg = chunk * (NN / KV_CHUNKS);
    for (int n0 = n_beg; n0 < n_beg + NN / KV_CHUNKS; n0 += 32) {
        fill_A_trans(As, Abase + (size_t)n0 * CC, CC, tid);
        fill_B(Bs, Bbase + (size_t)n0 * CC, CC, tid);
        __syncthreads();
        mma_tile(As, Bs, wm, wn, lane, c);
        __syncthreads();
    }
    float* outp = g_kv_part + ((size_t)chunk * BB * HH + bh) * DD * DD;
    const int g = lane >> 2, t = lane & 3;
#pragma unroll
    for (int mt = 0; mt < 4; mt++)
#pragma unroll
        for (int nt = 0; nt < 4; nt++) {
            const int col = wn * 32 + nt * 8 + 2 * t;
#pragma unroll
            for (int e = 0; e < 2; e++) {
                const int row = wm * 64 + mt * 16 + g + e * 8;
                *(float2*)(outp + row * DD + col) =
                    make_float2(c[mt][nt][2 * e], c[mt][nt][2 * e + 1]);
            }
        }
}

__global__ void kv_reduce_kernel()
{
    const int i = blockIdx.x * 256 + threadIdx.x;
    if (i >= BB * HH * DD * DD) return;
    float s = 0.f;
    for (int ch = 0; ch < KV_CHUNKS; ch++)
        s += g_kv_part[(size_t)ch * BB * HH * DD * DD + i];
    g_kv[i] = tf32f(s * (1.0f / 64.0f));
}

__global__ void __launch_bounds__(256)
out_tc(float* __restrict__ out)
{
    __shared__ unsigned As[128 * LDA_S];
    __shared__ unsigned Bs[32 * LDB_S];
    const int tid = threadIdx.x, lane = tid & 31, wid = tid >> 5;
    const int wm = wid >> 2, wn = wid & 3;
    const int rt = blockIdx.x;
    const int bh = blockIdx.y;
    const int b = bh >> 3, h = bh & 7;
    const float* Abase = g_qr + ((size_t)(b * NN + rt * 128)) * CC + h * 128;
    const float* Bbase = g_kv + (size_t)bh * DD * DD;
    float c[4][4][4] = {};
    for (int k0 = 0; k0 < DD; k0 += 32) {
        fill_A_rowmajor(As, Abase + k0, CC, tid);
        fill_B(Bs, Bbase + (size_t)k0 * DD, DD, tid);
        __syncthreads();
        mma_tile(As, Bs, wm, wn, lane, c);
        __syncthreads();
    }
    const int g = lane >> 2, t = lane & 3;
#pragma unroll
    for (int mt = 0; mt < 4; mt++)
#pragma unroll
        for (int e = 0; e < 2; e++) {
            const int n = rt * 128 + wm * 64 + mt * 16 + g + e * 8;
            const float zv = g_z[bh * NN + n];
            float* orow = out + ((size_t)(b * NN + n)) * CC + h * 128;
#pragma unroll
            for (int nt = 0; nt < 4; nt++) {
                const int col = wn * 32 + nt * 8 + 2 * t;
                *(float2*)(orow + col) =
                    make_float2(c[mt][nt][2 * e] * zv, c[mt][nt][2 * e + 1] * zv);
            }
        }
}

// ---------------- launch ----------------
extern "C" void kernel_launch(void* const* d_in, const int* in_sizes, int n_in,
                              void* d_out, int out_size)
{
    const float* x      = (const float*)d_in[0];
    const float* qk_w   = (const float*)d_in[1];
    const float* qk_b   = (const float*)d_in[2];
    const float* lepe_w = (const float*)d_in[3];
    const float* lepe_b = (const float*)d_in[4];
    float* out = (float*)d_out;

    static int attr_done = 0;
    if (!attr_done) {
        cudaFuncSetAttribute(gemm_qk_cp, cudaFuncAttributeMaxDynamicSharedMemorySize, DSMEM_BYTES);
        cudaFuncSetAttribute(lepe_cp,    cudaFuncAttributeMaxDynamicSharedMemorySize, DSMEM_BYTES);
        attr_done = 1;
    }

    float* d_xt;     cudaGetSymbolAddress((void**)&d_xt,     g_xt);
    float* d_qkwC;   cudaGetSymbolAddress((void**)&d_qkwC,   g_qkwC);
    float* d_lepewC; cudaGetSymbolAddress((void**)&d_lepewC, g_lepewC);

    cvt_tf32_kernel<<<M_TOT * CC / 1024, 256>>>(x, d_xt);
    cvt_tf32_kernel<<<2 * CC * CC / 1024, 256>>>(qk_w, d_qkwC);
    cvt_tf32_kernel<<<3 * CC * CC / 1024, 256>>>(lepe_w, d_lepewC);

    gemm_qk_cp<<<dim3(16, 128), 256, DSMEM_BYTES>>>(qk_b);
    rope_kernel<<<(M_TOT * 512) / 256, 256>>>();
    kmean_part_kernel<<<dim3(KM_CHUNKS, BB), 256>>>();
    kmean_fin_kernel<<<16, 256>>>();
    z_kernel<<<(BB * HH * NN * 32) / 256, 256>>>();
    kv_tc<<<dim3(KV_CHUNKS, BB * HH), 256>>>();
    kv_reduce_kernel<<<(BB * HH * DD * DD) / 256, 256>>>();
    out_tc<<<dim3(32, 32), 256>>>(out);
    lepe_cp<<<dim3(8, 128), 256, DSMEM_BYTES>>>(lepe_b, out);
}

// round 5
// speedup vs baseline: 4.4344x; 1.0629x over previous
#include <cuda_runtime.h>
#include <math.h>

#define BB 4
#define NN 4096
#define CC 1024
#define HH 8
#define DD 128
#define M_TOT (BB*NN)      // 16384
#define KV_CHUNKS 8
#define KM_CHUNKS 8

#define LDA_S 36
#define LDB_S 136

// qk/lepe/out GEMM smem geometry (bytes)
#define A_STAGE_B (128 * 144)      // 128 rows x 36 floats
#define B_STAGE_B (32 * 544)       // 32 rows x 136 floats
#define STAGE_B   (A_STAGE_B + B_STAGE_B)   // 35840
#define NSTAGE    3
#define DSMEM_BYTES (NSTAGE * STAGE_B)      // 107520

// kv GEMM smem geometry: two [32][136] tiles
#define KV_STAGE_B (2 * 32 * 544)           // 34816
#define KV_DSMEM   (NSTAGE * KV_STAGE_B)    // 104448

// ---------------- scratch ----------------
__device__ float g_qk[(size_t)M_TOT * 2 * CC];
__device__ float g_qr[(size_t)M_TOT * CC];
__device__ float g_kr[(size_t)M_TOT * CC];
__device__ float g_kmean_part[KM_CHUNKS * BB * CC];
__device__ float g_kmean[BB * CC];
__device__ float g_z[BB * HH * NN];
__device__ float g_kv_part[(size_t)KV_CHUNKS * BB * HH * DD * DD];
__device__ float g_kv[(size_t)BB * HH * DD * DD];
__device__ float g_xt[(size_t)M_TOT * CC];           // tf32-rounded x
__device__ float g_qkwC[(size_t)CC * 2 * CC];        // tf32-rounded qk_w
__device__ float g_lepewC[(size_t)3 * CC * CC];      // tf32-rounded lepe_w
__device__ float g_theta[512];

// ---------------- helpers ----------------
__device__ __forceinline__ unsigned tf32_of(float f)
{
    unsigned u;
    asm("cvt.rna.tf32.f32 %0, %1;" : "=r"(u) : "f"(f));
    return u;
}
__device__ __forceinline__ float tf32f(float f) { return __uint_as_float(tf32_of(f)); }
__device__ __forceinline__ unsigned sptr(const void* p)
{
    return (unsigned)__cvta_generic_to_shared(p);
}
__device__ __forceinline__ void cp16(unsigned dst, const void* src)
{
    asm volatile("cp.async.cg.shared.global [%0], [%1], 16;" :: "r"(dst), "l"(src));
}
__device__ __forceinline__ void cp16z(unsigned dst, const void* src, int sz)
{
    asm volatile("cp.async.cg.shared.global [%0], [%1], 16, %2;" :: "r"(dst), "l"(src), "r"(sz));
}
#define CP_COMMIT() asm volatile("cp.async.commit_group;" ::: "memory")
#define CP_WAIT1()  asm volatile("cp.async.wait_group 1;" ::: "memory")

// ---------------- prepasses ----------------
__global__ void cvt_tf32_kernel(const float* __restrict__ src, float* __restrict__ dst)
{
    const size_t i = ((size_t)blockIdx.x * blockDim.x + threadIdx.x) * 4;
    float4 v = *(const float4*)(src + i);
    *(float4*)(dst + i) = make_float4(tf32f(v.x), tf32f(v.y), tf32f(v.z), tf32f(v.w));
}

__global__ void theta_init_kernel()
{
    const int k = threadIdx.x;
    g_theta[k] = (float)exp(-(double)k * (log(10000.0) / 512.0));
}

// ---------------- warp-tile MMA: A from [m][k] ld36, B from [k][n] ld136 ----------------
__device__ __forceinline__ void mma_tile(const unsigned* As, const unsigned* Bs,
                                         int wm, int wn, int lane, float c[4][4][4])
{
    const int g = lane >> 2, t = lane & 3;
#pragma unroll
    for (int ks = 0; ks < 32; ks += 8) {
        unsigned a[4][4], b[4][2];
#pragma unroll
        for (int mt = 0; mt < 4; mt++) {
            const unsigned* p = As + (wm * 64 + mt * 16 + g) * LDA_S + ks + t;
            a[mt][0] = p[0];
            a[mt][1] = p[8 * LDA_S];
            a[mt][2] = p[4];
            a[mt][3] = p[8 * LDA_S + 4];
        }
#pragma unroll
        for (int nt = 0; nt < 4; nt++) {
            const unsigned* p = Bs + (ks + t) * LDB_S + wn * 32 + nt * 8 + g;
            b[nt][0] = p[0];
            b[nt][1] = p[4 * LDB_S];
        }
#pragma unroll
        for (int mt = 0; mt < 4; mt++)
#pragma unroll
            for (int nt = 0; nt < 4; nt++)
                asm volatile(
                    "mma.sync.aligned.m16n8k8.row.col.f32.tf32.tf32.f32 "
                    "{%0,%1,%2,%3},{%4,%5,%6,%7},{%8,%9},{%0,%1,%2,%3};"
                    : "+f"(c[mt][nt][0]), "+f"(c[mt][nt][1]),
                      "+f"(c[mt][nt][2]), "+f"(c[mt][nt][3])
                    : "r"(a[mt][0]), "r"(a[mt][1]), "r"(a[mt][2]), "r"(a[mt][3]),
                      "r"(b[nt][0]), "r"(b[nt][1]));
    }
}

// MMA with A gathered TRANSPOSED from [k][m] ld136 tile (for kv: A = kr^T)
__device__ __forceinline__ void mma_tile_kT(const unsigned* As, const unsigned* Bs,
                                            int wm, int wn, int lane, float c[4][4][4])
{
    const int g = lane >> 2, t = lane & 3;
#pragma unroll
    for (int ks = 0; ks < 32; ks += 8) {
        unsigned a[4][4], b[4][2];
#pragma unroll
        for (int mt = 0; mt < 4; mt++) {
            const int m = wm * 64 + mt * 16 + g;
            a[mt][0] = As[(ks + t) * LDB_S + m];
            a[mt][1] = As[(ks + t) * LDB_S + m + 8];
            a[mt][2] = As[(ks + t + 4) * LDB_S + m];
            a[mt][3] = As[(ks + t + 4) * LDB_S + m + 8];
        }
#pragma unroll
        for (int nt = 0; nt < 4; nt++) {
            const unsigned* p = Bs + (ks + t) * LDB_S + wn * 32 + nt * 8 + g;
            b[nt][0] = p[0];
            b[nt][1] = p[4 * LDB_S];
        }
#pragma unroll
        for (int mt = 0; mt < 4; mt++)
#pragma unroll
            for (int nt = 0; nt < 4; nt++)
                asm volatile(
                    "mma.sync.aligned.m16n8k8.row.col.f32.tf32.tf32.f32 "
                    "{%0,%1,%2,%3},{%4,%5,%6,%7},{%8,%9},{%0,%1,%2,%3};"
                    : "+f"(c[mt][nt][0]), "+f"(c[mt][nt][1]),
                      "+f"(c[mt][nt][2]), "+f"(c[mt][nt][3])
                    : "r"(a[mt][0]), "r"(a[mt][1]), "r"(a[mt][2]), "r"(a[mt][3]),
                      "r"(b[nt][0]), "r"(b[nt][1]));
    }
}

// ---------------- qk GEMM + fused bias/elu/rope epilogue ----------------
__global__ void __launch_bounds__(256, 2)
gemm_qk_cp(const float* __restrict__ bias)
{
    extern __shared__ __align__(16) char dsm[];
    const unsigned base = sptr(dsm);
    const int tid = threadIdx.x, lane = tid & 31, wid = tid >> 5;
    const int wm = wid >> 2, wn = wid & 3;
    const int br = blockIdx.y, bc = blockIdx.x;
    const float* Ab = g_xt + (size_t)br * 128 * CC;
    const float* Bw = g_qkwC + bc * 128;

    const int ar = tid >> 3, ac = tid & 7;
    const int brw = tid >> 5, bcw = tid & 31;

    auto fill = [&](int kt, int st) {
        const int k0 = kt * 32;
        const unsigned Abase = base + st * STAGE_B;
        const unsigned Bbase = Abase + A_STAGE_B;
#pragma unroll
        for (int i = 0; i < 4; i++) {
            const int r = ar + i * 32;
            cp16(Abase + r * 144 + ac * 16, Ab + (size_t)r * CC + k0 + ac * 4);
        }
#pragma unroll
        for (int i = 0; i < 4; i++) {
            const int r = brw + i * 8;
            cp16(Bbase + r * 544 + bcw * 16, Bw + (size_t)(k0 + r) * 2048 + bcw * 4);
        }
    };

    float c[4][4][4] = {};
    fill(0, 0); CP_COMMIT();
    fill(1, 1); CP_COMMIT();
    for (int kt = 0; kt < 32; kt++) {
        const int st = kt % NSTAGE;
        CP_WAIT1();
        __syncthreads();
        if (kt + 2 < 32) fill(kt + 2, (kt + 2) % NSTAGE);
        CP_COMMIT();
        const unsigned* As = (const unsigned*)(dsm + st * STAGE_B);
        const unsigned* Bs = (const unsigned*)(dsm + st * STAGE_B + A_STAGE_B);
        mma_tile(As, Bs, wm, wn, lane, c);
    }

    const int g = lane >> 2, t = lane & 3;
    const bool isq = (bc < 8);
    float* rdst = isq ? g_qr : g_kr;
#pragma unroll
    for (int nt = 0; nt < 4; nt++) {
        const int col = bc * 128 + wn * 32 + nt * 8 + 2 * t;
        const float b0 = bias[col], b1 = bias[col + 1];
        const int kp = (isq ? col : col - 1024) >> 1;
        const float theta = g_theta[kp];
#pragma unroll
        for (int mt = 0; mt < 4; mt++) {
#pragma unroll
            for (int e = 0; e < 2; e++) {
                const int row = br * 128 + wm * 64 + mt * 16 + g + e * 8;
                float v0 = c[mt][nt][2 * e]     + b0;
                float v1 = c[mt][nt][2 * e + 1] + b1;
                v0 = (v0 > 0.0f) ? (v0 + 1.0f) : expf(v0);
                v1 = (v1 > 0.0f) ? (v1 + 1.0f) : expf(v1);
                *(float2*)(g_qk + (size_t)row * 2048 + col) = make_float2(v0, v1);
                const int n = row & (NN - 1);
                float s, cw;
                sincosf((float)n * theta, &s, &cw);
                rdst[(size_t)row * 1024 + kp]       = tf32f(cw * v0 - s * v1);
                rdst[(size_t)row * 1024 + 512 + kp] = tf32f(cw * v1 + s * v0);
            }
        }
    }
}

// ---------------- lepe conv GEMM ----------------
__global__ void __launch_bounds__(256, 2)
lepe_cp(const float* __restrict__ bias, float* __restrict__ out)
{
    extern __shared__ __align__(16) char dsm[];
    const unsigned base = sptr(dsm);
    const int tid = threadIdx.x, lane = tid & 31, wid = tid >> 5;
    const int wm = wid >> 2, wn = wid & 3;
    const int br = blockIdx.y, bc = blockIdx.x;
    const int m0 = br * 128;

    const int ar = tid >> 3, ac = tid & 7;
    const int brw = tid >> 5, bcw = tid & 31;

    auto fill = [&](int kt, int st) {
        const int tap = kt >> 5;
        const int k0 = (kt & 31) * 32;
        const float* Bw = g_lepewC + (size_t)tap * CC * CC + bc * 128;
        const unsigned Abase = base + st * STAGE_B;
        const unsigned Bbase = Abase + A_STAGE_B;
#pragma unroll
        for (int i = 0; i < 4; i++) {
            const int r = ar + i * 32;
            const int m = m0 + r;
            int n = (m & (NN - 1)) + tap - 1;
            const int b = m >> 12;
            const bool valid = (n >= 0) && (n < NN);
            if (!valid) n = 0;
            cp16z(Abase + r * 144 + ac * 16,
                  g_xt + ((size_t)(b * NN + n)) * CC + k0 + ac * 4, valid ? 16 : 0);
        }
#pragma unroll
        for (int i = 0; i < 4; i++) {
            const int r = brw + i * 8;
            cp16(Bbase + r * 544 + bcw * 16, Bw + (size_t)(k0 + r) * CC + bcw * 4);
        }
    };

    float c[4][4][4] = {};
    fill(0, 0); CP_COMMIT();
    fill(1, 1); CP_COMMIT();
    for (int kt = 0; kt < 96; kt++) {
        const int st = kt % NSTAGE;
        CP_WAIT1();
        __syncthreads();
        if (kt + 2 < 96) fill(kt + 2, (kt + 2) % NSTAGE);
        CP_COMMIT();
        const unsigned* As = (const unsigned*)(dsm + st * STAGE_B);
        const unsigned* Bs = (const unsigned*)(dsm + st * STAGE_B + A_STAGE_B);
        mma_tile(As, Bs, wm, wn, lane, c);
    }

    const int g = lane >> 2, t = lane & 3;
#pragma unroll
    for (int mt = 0; mt < 4; mt++)
#pragma unroll
        for (int nt = 0; nt < 4; nt++) {
            const int col = bc * 128 + wn * 32 + nt * 8 + 2 * t;
            const float b0 = bias[col], b1 = bias[col + 1];
#pragma unroll
            for (int e = 0; e < 2; e++) {
                const int row = m0 + wm * 64 + mt * 16 + g + e * 8;
                float* p = out + (size_t)row * CC + col;
                float2 old = *(float2*)p;
                *(float2*)p = make_float2(old.x + c[mt][nt][2 * e] + b0,
                                          old.y + c[mt][nt][2 * e + 1] + b1);
            }
        }
}

// ---------------- kv GEMM: kv[d,e] = sum_n kr[n,d] x[n,e], pipelined ----------------
__global__ void __launch_bounds__(256, 2)
kv_cp()
{
    extern __shared__ __align__(16) char dsm[];
    const unsigned base = sptr(dsm);
    const int tid = threadIdx.x, lane = tid & 31, wid = tid >> 5;
    const int wm = wid >> 2, wn = wid & 3;
    const int chunk = blockIdx.x;
    const int bh = blockIdx.y;
    const int b = bh >> 3, h = bh & 7;
    const int n_base = chunk * (NN / KV_CHUNKS);
    const float* Akr = g_kr + ((size_t)b * NN) * CC + h * 128;
    const float* Bx  = g_xt + ((size_t)b * NN) * CC + h * 128;

    const int rr = tid >> 5, rc = tid & 31;

    auto fill = [&](int kt, int st) {
        const int n0 = n_base + kt * 32;
        const unsigned Abase = base + st * KV_STAGE_B;
        const unsigned Bbase = Abase + 32 * 544;
#pragma unroll
        for (int i = 0; i < 4; i++) {
            const int r = rr + i * 8;
            cp16(Abase + r * 544 + rc * 16, Akr + (size_t)(n0 + r) * CC + rc * 4);
            cp16(Bbase + r * 544 + rc * 16, Bx  + (size_t)(n0 + r) * CC + rc * 4);
        }
    };

    float c[4][4][4] = {};
    fill(0, 0); CP_COMMIT();
    fill(1, 1); CP_COMMIT();
    const int NT = (NN / KV_CHUNKS) / 32;   // 16
    for (int kt = 0; kt < NT; kt++) {
        const int st = kt % NSTAGE;
        CP_WAIT1();
        __syncthreads();
        if (kt + 2 < NT) fill(kt + 2, (kt + 2) % NSTAGE);
        CP_COMMIT();
        const unsigned* As = (const unsigned*)(dsm + st * KV_STAGE_B);
        const unsigned* Bs = (const unsigned*)(dsm + st * KV_STAGE_B + 32 * 544);
        mma_tile_kT(As, Bs, wm, wn, lane, c);
    }

    float* outp = g_kv_part + ((size_t)chunk * BB * HH + bh) * DD * DD;
    const int g = lane >> 2, t = lane & 3;
#pragma unroll
    for (int mt = 0; mt < 4; mt++)
#pragma unroll
        for (int nt = 0; nt < 4; nt++) {
            const int col = wn * 32 + nt * 8 + 2 * t;
#pragma unroll
            for (int e = 0; e < 2; e++) {
                const int row = wm * 64 + mt * 16 + g + e * 8;
                *(float2*)(outp + row * DD + col) =
                    make_float2(c[mt][nt][2 * e], c[mt][nt][2 * e + 1]);
            }
        }
}

__global__ void kv_reduce_kernel()
{
    const int i = blockIdx.x * 256 + threadIdx.x;
    if (i >= BB * HH * DD * DD) return;
    float s = 0.f;
    for (int ch = 0; ch < KV_CHUNKS; ch++)
        s += g_kv_part[(size_t)ch * BB * HH * DD * DD + i];
    g_kv[i] = tf32f(s * (1.0f / 64.0f));
}

// ---------------- out = (qr @ kv) * z, pipelined ----------------
__global__ void __launch_bounds__(256, 2)
out_cp(float* __restrict__ out)
{
    extern __shared__ __align__(16) char dsm[];
    const unsigned base = sptr(dsm);
    const int tid = threadIdx.x, lane = tid & 31, wid = tid >> 5;
    const int wm = wid >> 2, wn = wid & 3;
    const int rt = blockIdx.x;
    const int bh = blockIdx.y;
    const int b = bh >> 3, h = bh & 7;
    const float* Aq = g_qr + ((size_t)(b * NN + rt * 128)) * CC + h * 128;
    const float* Bk = g_kv + (size_t)bh * DD * DD;

    const int ar = tid >> 3, ac = tid & 7;
    const int brw = tid >> 5, bcw = tid & 31;

    auto fill = [&](int kt, int st) {
        const int k0 = kt * 32;
        const unsigned Abase = base + st * STAGE_B;
        const unsigned Bbase = Abase + A_STAGE_B;
#pragma unroll
        for (int i = 0; i < 4; i++) {
            const int r = ar + i * 32;
            cp16(Abase + r * 144 + ac * 16, Aq + (size_t)r * CC + k0 + ac * 4);
        }
#pragma unroll
        for (int i = 0; i < 4; i++) {
            const int r = brw + i * 8;
            cp16(Bbase + r * 544 + bcw * 16, Bk + (size_t)(k0 + r) * DD + bcw * 4);
        }
    };

    float c[4][4][4] = {};
    fill(0, 0); CP_COMMIT();
    fill(1, 1); CP_COMMIT();
    for (int kt = 0; kt < 4; kt++) {
        const int st = kt % NSTAGE;
        CP_WAIT1();
        __syncthreads();
        if (kt + 2 < 4) fill(kt + 2, (kt + 2) % NSTAGE);
        CP_COMMIT();
        const unsigned* As = (const unsigned*)(dsm + st * STAGE_B);
        const unsigned* Bs = (const unsigned*)(dsm + st * STAGE_B + A_STAGE_B);
        mma_tile(As, Bs, wm, wn, lane, c);
    }

    const int g = lane >> 2, t = lane & 3;
#pragma unroll
    for (int mt = 0; mt < 4; mt++)
#pragma unroll
        for (int e = 0; e < 2; e++) {
            const int n = rt * 128 + wm * 64 + mt * 16 + g + e * 8;
            const float zv = g_z[bh * NN + n];
            float* orow = out + ((size_t)(b * NN + n)) * CC + h * 128;
#pragma unroll
            for (int nt = 0; nt < 4; nt++) {
                const int col = wn * 32 + nt * 8 + 2 * t;
                *(float2*)(orow + col) =
                    make_float2(c[mt][nt][2 * e] * zv, c[mt][nt][2 * e + 1] * zv);
            }
        }
}

// ---------------- k mean ----------------
__global__ void kmean_part_kernel()
{
    const int chunk = blockIdx.x;
    const int b = blockIdx.y;
    const int c4 = threadIdx.x * 4;
    float4 s = make_float4(0.f, 0.f, 0.f, 0.f);
    for (int n = chunk * (NN / KM_CHUNKS); n < (chunk + 1) * (NN / KM_CHUNKS); n++) {
        const float4 v = *(const float4*)(g_qk + ((size_t)(b * NN + n)) * 2048 + 1024 + c4);
        s.x += v.x; s.y += v.y; s.z += v.z; s.w += v.w;
    }
    *(float4*)(&g_kmean_part[(chunk * BB + b) * CC + c4]) = s;
}

__global__ void kmean_fin_kernel()
{
    const int i = blockIdx.x * 256 + threadIdx.x;
    if (i >= BB * CC) return;
    float s = 0.f;
    for (int ch = 0; ch < KM_CHUNKS; ch++) s += g_kmean_part[ch * BB * CC + i];
    g_kmean[i] = s * (1.0f / NN);
}

// ---------------- z = 1 / (q . k_mean + 1e-6) ----------------
__global__ void z_kernel()
{
    const int gw = (blockIdx.x * blockDim.x + threadIdx.x) >> 5;
    const int lane = threadIdx.x & 31;
    if (gw >= BB * HH * NN) return;
    const int n = gw & (NN - 1);
    const int h = (gw >> 12) & 7;
    const int b = gw >> 15;
    const float* qrow = g_qk + ((size_t)(b * NN + n)) * 2048 + h * 128;
    const float* km = g_kmean + b * CC + h * 128;
    const float4 qv = *(const float4*)(qrow + lane * 4);
    const float4 kv = *(const float4*)(km + lane * 4);
    float s = qv.x * kv.x + qv.y * kv.y + qv.z * kv.z + qv.w * kv.w;
#pragma unroll
    for (int o = 16; o; o >>= 1) s += __shfl_xor_sync(0xffffffffu, s, o);
    if (lane == 0) g_z[gw] = 1.0f / (s + 1e-6f);
}

// ---------------- launch ----------------
extern "C" void kernel_launch(void* const* d_in, const int* in_sizes, int n_in,
                              void* d_out, int out_size)
{
    const float* x      = (const float*)d_in[0];
    const float* qk_w   = (const float*)d_in[1];
    const float* qk_b   = (const float*)d_in[2];
    const float* lepe_w = (const float*)d_in[3];
    const float* lepe_b = (const float*)d_in[4];
    float* out = (float*)d_out;

    static int attr_done = 0;
    if (!attr_done) {
        cudaFuncSetAttribute(gemm_qk_cp, cudaFuncAttributeMaxDynamicSharedMemorySize, DSMEM_BYTES);
        cudaFuncSetAttribute(lepe_cp,    cudaFuncAttributeMaxDynamicSharedMemorySize, DSMEM_BYTES);
        cudaFuncSetAttribute(kv_cp,      cudaFuncAttributeMaxDynamicSharedMemorySize, KV_DSMEM);
        cudaFuncSetAttribute(out_cp,     cudaFuncAttributeMaxDynamicSharedMemorySize, DSMEM_BYTES);
        attr_done = 1;
    }

    float* d_xt;     cudaGetSymbolAddress((void**)&d_xt,     g_xt);
    float* d_qkwC;   cudaGetSymbolAddress((void**)&d_qkwC,   g_qkwC);
    float* d_lepewC; cudaGetSymbolAddress((void**)&d_lepewC, g_lepewC);

    theta_init_kernel<<<1, 512>>>();
    cvt_tf32_kernel<<<M_TOT * CC / 1024, 256>>>(x, d_xt);
    cvt_tf32_kernel<<<2 * CC * CC / 1024, 256>>>(qk_w, d_qkwC);
    cvt_tf32_kernel<<<3 * CC * CC / 1024, 256>>>(lepe_w, d_lepewC);

    gemm_qk_cp<<<dim3(16, 128), 256, DSMEM_BYTES>>>(qk_b);
    kmean_part_kernel<<<dim3(KM_CHUNKS, BB), 256>>>();
    kmean_fin_kernel<<<16, 256>>>();
    z_kernel<<<(BB * HH * NN * 32) / 256, 256>>>();
    kv_cp<<<dim3(KV_CHUNKS, BB * HH), 256, KV_DSMEM>>>();
    kv_reduce_kernel<<<(BB * HH * DD * DD) / 256, 256>>>();
    out_cp<<<dim3(32, 32), 256, DSMEM_BYTES>>>(out);
    lepe_cp<<<dim3(8, 128), 256, DSMEM_BYTES>>>(lepe_b, out);
}

// round 6
// speedup vs baseline: 4.8092x; 1.0845x over previous
#include <cuda_runtime.h>
#include <math.h>

#define BB 4
#define NN 4096
#define CC 1024
#define HH 8
#define DD 128
#define M_TOT (BB*NN)      // 16384
#define KV_CHUNKS 8
#define KM_CHUNKS 64

#define LDA_S 36
#define LDB_S 136

// qk/lepe/out GEMM smem geometry (bytes)
#define A_STAGE_B (128 * 144)      // 128 rows x 36 floats
#define B_STAGE_B (32 * 544)       // 32 rows x 136 floats
#define STAGE_B   (A_STAGE_B + B_STAGE_B)   // 35840
#define NSTAGE    3
#define DSMEM_BYTES (NSTAGE * STAGE_B)      // 107520

// kv GEMM smem geometry: two [32][136] tiles
#define KV_STAGE_B (2 * 32 * 544)           // 34816
#define KV_DSMEM   (NSTAGE * KV_STAGE_B)    // 104448

// ---------------- scratch ----------------
__device__ float g_qk[(size_t)M_TOT * 2 * CC];
__device__ float g_qr[(size_t)M_TOT * CC];
__device__ float g_kr[(size_t)M_TOT * CC];
__device__ float g_lepe[(size_t)M_TOT * CC];
__device__ float g_kmean_part[KM_CHUNKS * BB * CC];
__device__ float g_kmean[BB * CC];
__device__ float g_z[BB * HH * NN];
__device__ float g_kv_part[(size_t)KV_CHUNKS * BB * HH * DD * DD];
__device__ float g_kv[(size_t)BB * HH * DD * DD];
__device__ float g_xt[(size_t)M_TOT * CC];           // tf32-rounded x
__device__ float g_qkwC[(size_t)CC * 2 * CC];        // tf32-rounded qk_w
__device__ float g_lepewC[(size_t)3 * CC * CC];      // tf32-rounded lepe_w
__device__ float g_theta[512];

// ---------------- helpers ----------------
__device__ __forceinline__ unsigned tf32_of(float f)
{
    unsigned u;
    asm("cvt.rna.tf32.f32 %0, %1;" : "=r"(u) : "f"(f));
    return u;
}
__device__ __forceinline__ float tf32f(float f) { return __uint_as_float(tf32_of(f)); }
__device__ __forceinline__ unsigned sptr(const void* p)
{
    return (unsigned)__cvta_generic_to_shared(p);
}
__device__ __forceinline__ void cp16(unsigned dst, const void* src)
{
    asm volatile("cp.async.cg.shared.global [%0], [%1], 16;" :: "r"(dst), "l"(src));
}
__device__ __forceinline__ void cp16z(unsigned dst, const void* src, int sz)
{
    asm volatile("cp.async.cg.shared.global [%0], [%1], 16, %2;" :: "r"(dst), "l"(src), "r"(sz));
}
#define CP_COMMIT() asm volatile("cp.async.commit_group;" ::: "memory")
#define CP_WAIT1()  asm volatile("cp.async.wait_group 1;" ::: "memory")

// ---------------- prepasses ----------------
__global__ void cvt_tf32_kernel(const float* __restrict__ src, float* __restrict__ dst)
{
    const size_t i = ((size_t)blockIdx.x * blockDim.x + threadIdx.x) * 4;
    float4 v = *(const float4*)(src + i);
    *(float4*)(dst + i) = make_float4(tf32f(v.x), tf32f(v.y), tf32f(v.z), tf32f(v.w));
}

__global__ void theta_init_kernel()
{
    const int k = threadIdx.x;
    g_theta[k] = (float)exp(-(double)k * (log(10000.0) / 512.0));
}

// ---------------- warp-tile MMA: A from [m][k] ld36, B from [k][n] ld136 ----------------
__device__ __forceinline__ void mma_tile(const unsigned* As, const unsigned* Bs,
                                         int wm, int wn, int lane, float c[4][4][4])
{
    const int g = lane >> 2, t = lane & 3;
#pragma unroll
    for (int ks = 0; ks < 32; ks += 8) {
        unsigned a[4][4], b[4][2];
#pragma unroll
        for (int mt = 0; mt < 4; mt++) {
            const unsigned* p = As + (wm * 64 + mt * 16 + g) * LDA_S + ks + t;
            a[mt][0] = p[0];
            a[mt][1] = p[8 * LDA_S];
            a[mt][2] = p[4];
            a[mt][3] = p[8 * LDA_S + 4];
        }
#pragma unroll
        for (int nt = 0; nt < 4; nt++) {
            const unsigned* p = Bs + (ks + t) * LDB_S + wn * 32 + nt * 8 + g;
            b[nt][0] = p[0];
            b[nt][1] = p[4 * LDB_S];
        }
#pragma unroll
        for (int mt = 0; mt < 4; mt++)
#pragma unroll
            for (int nt = 0; nt < 4; nt++)
                asm volatile(
                    "mma.sync.aligned.m16n8k8.row.col.f32.tf32.tf32.f32 "
                    "{%0,%1,%2,%3},{%4,%5,%6,%7},{%8,%9},{%0,%1,%2,%3};"
                    : "+f"(c[mt][nt][0]), "+f"(c[mt][nt][1]),
                      "+f"(c[mt][nt][2]), "+f"(c[mt][nt][3])
                    : "r"(a[mt][0]), "r"(a[mt][1]), "r"(a[mt][2]), "r"(a[mt][3]),
                      "r"(b[nt][0]), "r"(b[nt][1]));
    }
}

// MMA with A gathered TRANSPOSED from [k][m] ld136 tile (for kv: A = kr^T)
__device__ __forceinline__ void mma_tile_kT(const unsigned* As, const unsigned* Bs,
                                            int wm, int wn, int lane, float c[4][4][4])
{
    const int g = lane >> 2, t = lane & 3;
#pragma unroll
    for (int ks = 0; ks < 32; ks += 8) {
        unsigned a[4][4], b[4][2];
#pragma unroll
        for (int mt = 0; mt < 4; mt++) {
            const int m = wm * 64 + mt * 16 + g;
            a[mt][0] = As[(ks + t) * LDB_S + m];
            a[mt][1] = As[(ks + t) * LDB_S + m + 8];
            a[mt][2] = As[(ks + t + 4) * LDB_S + m];
            a[mt][3] = As[(ks + t + 4) * LDB_S + m + 8];
        }
#pragma unroll
        for (int nt = 0; nt < 4; nt++) {
            const unsigned* p = Bs + (ks + t) * LDB_S + wn * 32 + nt * 8 + g;
            b[nt][0] = p[0];
            b[nt][1] = p[4 * LDB_S];
        }
#pragma unroll
        for (int mt = 0; mt < 4; mt++)
#pragma unroll
            for (int nt = 0; nt < 4; nt++)
                asm volatile(
                    "mma.sync.aligned.m16n8k8.row.col.f32.tf32.tf32.f32 "
                    "{%0,%1,%2,%3},{%4,%5,%6,%7},{%8,%9},{%0,%1,%2,%3};"
                    : "+f"(c[mt][nt][0]), "+f"(c[mt][nt][1]),
                      "+f"(c[mt][nt][2]), "+f"(c[mt][nt][3])
                    : "r"(a[mt][0]), "r"(a[mt][1]), "r"(a[mt][2]), "r"(a[mt][3]),
                      "r"(b[nt][0]), "r"(b[nt][1]));
    }
}

// ---------------- qk GEMM + fused bias/elu/rope epilogue ----------------
__global__ void __launch_bounds__(256, 2)
gemm_qk_cp(const float* __restrict__ bias)
{
    extern __shared__ __align__(16) char dsm[];
    const unsigned base = sptr(dsm);
    const int tid = threadIdx.x, lane = tid & 31, wid = tid >> 5;
    const int wm = wid >> 2, wn = wid & 3;
    const int br = blockIdx.y, bc = blockIdx.x;
    const float* Ab = g_xt + (size_t)br * 128 * CC;
    const float* Bw = g_qkwC + bc * 128;

    const int ar = tid >> 3, ac = tid & 7;
    const int brw = tid >> 5, bcw = tid & 31;

    auto fill = [&](int kt, int st) {
        const int k0 = kt * 32;
        const unsigned Abase = base + st * STAGE_B;
        const unsigned Bbase = Abase + A_STAGE_B;
#pragma unroll
        for (int i = 0; i < 4; i++) {
            const int r = ar + i * 32;
            cp16(Abase + r * 144 + ac * 16, Ab + (size_t)r * CC + k0 + ac * 4);
        }
#pragma unroll
        for (int i = 0; i < 4; i++) {
            const int r = brw + i * 8;
            cp16(Bbase + r * 544 + bcw * 16, Bw + (size_t)(k0 + r) * 2048 + bcw * 4);
        }
    };

    float c[4][4][4] = {};
    fill(0, 0); CP_COMMIT();
    fill(1, 1); CP_COMMIT();
    for (int kt = 0; kt < 32; kt++) {
        const int st = kt % NSTAGE;
        CP_WAIT1();
        __syncthreads();
        if (kt + 2 < 32) fill(kt + 2, (kt + 2) % NSTAGE);
        CP_COMMIT();
        const unsigned* As = (const unsigned*)(dsm + st * STAGE_B);
        const unsigned* Bs = (const unsigned*)(dsm + st * STAGE_B + A_STAGE_B);
        mma_tile(As, Bs, wm, wn, lane, c);
    }

    const int g = lane >> 2, t = lane & 3;
    const bool isq = (bc < 8);
    float* rdst = isq ? g_qr : g_kr;
#pragma unroll
    for (int nt = 0; nt < 4; nt++) {
        const int col = bc * 128 + wn * 32 + nt * 8 + 2 * t;
        const float b0 = bias[col], b1 = bias[col + 1];
        const int kp = (isq ? col : col - 1024) >> 1;
        const float theta = g_theta[kp];
#pragma unroll
        for (int mt = 0; mt < 4; mt++) {
#pragma unroll
            for (int e = 0; e < 2; e++) {
                const int row = br * 128 + wm * 64 + mt * 16 + g + e * 8;
                float v0 = c[mt][nt][2 * e]     + b0;
                float v1 = c[mt][nt][2 * e + 1] + b1;
                v0 = (v0 > 0.0f) ? (v0 + 1.0f) : expf(v0);
                v1 = (v1 > 0.0f) ? (v1 + 1.0f) : expf(v1);
                *(float2*)(g_qk + (size_t)row * 2048 + col) = make_float2(v0, v1);
                const int n = row & (NN - 1);
                float s, cw;
                sincosf((float)n * theta, &s, &cw);
                rdst[(size_t)row * 1024 + kp]       = tf32f(cw * v0 - s * v1);
                rdst[(size_t)row * 1024 + 512 + kp] = tf32f(cw * v1 + s * v0);
            }
        }
    }
}

// ---------------- lepe conv GEMM -> g_lepe (no bias, no RMW) ----------------
__global__ void __launch_bounds__(256, 2)
lepe_cp()
{
    extern __shared__ __align__(16) char dsm[];
    const unsigned base = sptr(dsm);
    const int tid = threadIdx.x, lane = tid & 31, wid = tid >> 5;
    const int wm = wid >> 2, wn = wid & 3;
    const int br = blockIdx.y, bc = blockIdx.x;
    const int m0 = br * 128;

    const int ar = tid >> 3, ac = tid & 7;
    const int brw = tid >> 5, bcw = tid & 31;

    auto fill = [&](int kt, int st) {
        const int tap = kt >> 5;
        const int k0 = (kt & 31) * 32;
        const float* Bw = g_lepewC + (size_t)tap * CC * CC + bc * 128;
        const unsigned Abase = base + st * STAGE_B;
        const unsigned Bbase = Abase + A_STAGE_B;
#pragma unroll
        for (int i = 0; i < 4; i++) {
            const int r = ar + i * 32;
            const int m = m0 + r;
            int n = (m & (NN - 1)) + tap - 1;
            const int b = m >> 12;
            const bool valid = (n >= 0) && (n < NN);
            if (!valid) n = 0;
            cp16z(Abase + r * 144 + ac * 16,
                  g_xt + ((size_t)(b * NN + n)) * CC + k0 + ac * 4, valid ? 16 : 0);
        }
#pragma unroll
        for (int i = 0; i < 4; i++) {
            const int r = brw + i * 8;
            cp16(Bbase + r * 544 + bcw * 16, Bw + (size_t)(k0 + r) * CC + bcw * 4);
        }
    };

    float c[4][4][4] = {};
    fill(0, 0); CP_COMMIT();
    fill(1, 1); CP_COMMIT();
    for (int kt = 0; kt < 96; kt++) {
        const int st = kt % NSTAGE;
        CP_WAIT1();
        __syncthreads();
        if (kt + 2 < 96) fill(kt + 2, (kt + 2) % NSTAGE);
        CP_COMMIT();
        const unsigned* As = (const unsigned*)(dsm + st * STAGE_B);
        const unsigned* Bs = (const unsigned*)(dsm + st * STAGE_B + A_STAGE_B);
        mma_tile(As, Bs, wm, wn, lane, c);
    }

    const int g = lane >> 2, t = lane & 3;
#pragma unroll
    for (int mt = 0; mt < 4; mt++)
#pragma unroll
        for (int nt = 0; nt < 4; nt++) {
            const int col = bc * 128 + wn * 32 + nt * 8 + 2 * t;
#pragma unroll
            for (int e = 0; e < 2; e++) {
                const int row = m0 + wm * 64 + mt * 16 + g + e * 8;
                *(float2*)(g_lepe + (size_t)row * CC + col) =
                    make_float2(c[mt][nt][2 * e], c[mt][nt][2 * e + 1]);
            }
        }
}

// ---------------- kv GEMM: kv[d,e] = sum_n kr[n,d] x[n,e], pipelined ----------------
__global__ void __launch_bounds__(256, 2)
kv_cp()
{
    extern __shared__ __align__(16) char dsm[];
    const unsigned base = sptr(dsm);
    const int tid = threadIdx.x, lane = tid & 31, wid = tid >> 5;
    const int wm = wid >> 2, wn = wid & 3;
    const int chunk = blockIdx.x;
    const int bh = blockIdx.y;
    const int b = bh >> 3, h = bh & 7;
    const int n_base = chunk * (NN / KV_CHUNKS);
    const float* Akr = g_kr + ((size_t)b * NN) * CC + h * 128;
    const float* Bx  = g_xt + ((size_t)b * NN) * CC + h * 128;

    const int rr = tid >> 5, rc = tid & 31;

    auto fill = [&](int kt, int st) {
        const int n0 = n_base + kt * 32;
        const unsigned Abase = base + st * KV_STAGE_B;
        const unsigned Bbase = Abase + 32 * 544;
#pragma unroll
        for (int i = 0; i < 4; i++) {
            const int r = rr + i * 8;
            cp16(Abase + r * 544 + rc * 16, Akr + (size_t)(n0 + r) * CC + rc * 4);
            cp16(Bbase + r * 544 + rc * 16, Bx  + (size_t)(n0 + r) * CC + rc * 4);
        }
    };

    float c[4][4][4] = {};
    fill(0, 0); CP_COMMIT();
    fill(1, 1); CP_COMMIT();
    const int NT = (NN / KV_CHUNKS) / 32;   // 16
    for (int kt = 0; kt < NT; kt++) {
        const int st = kt % NSTAGE;
        CP_WAIT1();
        __syncthreads();
        if (kt + 2 < NT) fill(kt + 2, (kt + 2) % NSTAGE);
        CP_COMMIT();
        const unsigned* As = (const unsigned*)(dsm + st * KV_STAGE_B);
        const unsigned* Bs = (const unsigned*)(dsm + st * KV_STAGE_B + 32 * 544);
        mma_tile_kT(As, Bs, wm, wn, lane, c);
    }

    float* outp = g_kv_part + ((size_t)chunk * BB * HH + bh) * DD * DD;
    const int g = lane >> 2, t = lane & 3;
#pragma unroll
    for (int mt = 0; mt < 4; mt++)
#pragma unroll
        for (int nt = 0; nt < 4; nt++) {
            const int col = wn * 32 + nt * 8 + 2 * t;
#pragma unroll
            for (int e = 0; e < 2; e++) {
                const int row = wm * 64 + mt * 16 + g + e * 8;
                *(float2*)(outp + row * DD + col) =
                    make_float2(c[mt][nt][2 * e], c[mt][nt][2 * e + 1]);
            }
        }
}

__global__ void kv_reduce_kernel()
{
    const int i = blockIdx.x * 256 + threadIdx.x;
    if (i >= BB * HH * DD * DD) return;
    float s = 0.f;
    for (int ch = 0; ch < KV_CHUNKS; ch++)
        s += g_kv_part[(size_t)ch * BB * HH * DD * DD + i];
    g_kv[i] = tf32f(s * (1.0f / 64.0f));
}

// ---------------- out = (qr @ kv) * z + lepe + lepe_b ----------------
__global__ void __launch_bounds__(256, 2)
out_cp(float* __restrict__ out, const float* __restrict__ lbias)
{
    extern __shared__ __align__(16) char dsm[];
    const unsigned base = sptr(dsm);
    const int tid = threadIdx.x, lane = tid & 31, wid = tid >> 5;
    const int wm = wid >> 2, wn = wid & 3;
    const int rt = blockIdx.x;
    const int bh = blockIdx.y;
    const int b = bh >> 3, h = bh & 7;
    const float* Aq = g_qr + ((size_t)(b * NN + rt * 128)) * CC + h * 128;
    const float* Bk = g_kv + (size_t)bh * DD * DD;

    const int ar = tid >> 3, ac = tid & 7;
    const int brw = tid >> 5, bcw = tid & 31;

    auto fill = [&](int kt, int st) {
        const int k0 = kt * 32;
        const unsigned Abase = base + st * STAGE_B;
        const unsigned Bbase = Abase + A_STAGE_B;
#pragma unroll
        for (int i = 0; i < 4; i++) {
            const int r = ar + i * 32;
            cp16(Abase + r * 144 + ac * 16, Aq + (size_t)r * CC + k0 + ac * 4);
        }
#pragma unroll
        for (int i = 0; i < 4; i++) {
            const int r = brw + i * 8;
            cp16(Bbase + r * 544 + bcw * 16, Bk + (size_t)(k0 + r) * DD + bcw * 4);
        }
    };

    float c[4][4][4] = {};
    fill(0, 0); CP_COMMIT();
    fill(1, 1); CP_COMMIT();
    for (int kt = 0; kt < 4; kt++) {
        const int st = kt % NSTAGE;
        CP_WAIT1();
        __syncthreads();
        if (kt + 2 < 4) fill(kt + 2, (kt + 2) % NSTAGE);
        CP_COMMIT();
        const unsigned* As = (const unsigned*)(dsm + st * STAGE_B);
        const unsigned* Bs = (const unsigned*)(dsm + st * STAGE_B + A_STAGE_B);
        mma_tile(As, Bs, wm, wn, lane, c);
    }

    const int g = lane >> 2, t = lane & 3;
#pragma unroll
    for (int mt = 0; mt < 4; mt++)
#pragma unroll
        for (int e = 0; e < 2; e++) {
            const int n = rt * 128 + wm * 64 + mt * 16 + g + e * 8;
            const float zv = g_z[bh * NN + n];
            const size_t rowoff = ((size_t)(b * NN + n)) * CC + h * 128;
            float* orow = out + rowoff;
            const float* lrow = g_lepe + rowoff;
#pragma unroll
            for (int nt = 0; nt < 4; nt++) {
                const int col = wn * 32 + nt * 8 + 2 * t;
                const float2 lv = *(const float2*)(lrow + col);
                const float lb0 = lbias[h * 128 + col];
                const float lb1 = lbias[h * 128 + col + 1];
                *(float2*)(orow + col) =
                    make_float2(c[mt][nt][2 * e] * zv + lv.x + lb0,
                                c[mt][nt][2 * e + 1] * zv + lv.y + lb1);
            }
        }
}

// ---------------- k mean ----------------
__global__ void kmean_part_kernel()
{
    const int chunk = blockIdx.x;
    const int b = blockIdx.y;
    const int c4 = threadIdx.x * 4;
    float4 s = make_float4(0.f, 0.f, 0.f, 0.f);
    for (int n = chunk * (NN / KM_CHUNKS); n < (chunk + 1) * (NN / KM_CHUNKS); n++) {
        const float4 v = *(const float4*)(g_qk + ((size_t)(b * NN + n)) * 2048 + 1024 + c4);
        s.x += v.x; s.y += v.y; s.z += v.z; s.w += v.w;
    }
    *(float4*)(&g_kmean_part[(chunk * BB + b) * CC + c4]) = s;
}

__global__ void kmean_fin_kernel()
{
    const int i = blockIdx.x * 256 + threadIdx.x;
    if (i >= BB * CC) return;
    float s = 0.f;
    for (int ch = 0; ch < KM_CHUNKS; ch++) s += g_kmean_part[ch * BB * CC + i];
    g_kmean[i] = s * (1.0f / NN);
}

// ---------------- z = 1 / (q . k_mean + 1e-6) ----------------
__global__ void z_kernel()
{
    const int gw = (blockIdx.x * blockDim.x + threadIdx.x) >> 5;
    const int lane = threadIdx.x & 31;
    if (gw >= BB * HH * NN) return;
    const int n = gw & (NN - 1);
    const int h = (gw >> 12) & 7;
    const int b = gw >> 15;
    const float* qrow = g_qk + ((size_t)(b * NN + n)) * 2048 + h * 128;
    const float* km = g_kmean + b * CC + h * 128;
    const float4 qv = *(const float4*)(qrow + lane * 4);
    const float4 kv = *(const float4*)(km + lane * 4);
    float s = qv.x * kv.x + qv.y * kv.y + qv.z * kv.z + qv.w * kv.w;
#pragma unroll
    for (int o = 16; o; o >>= 1) s += __shfl_xor_sync(0xffffffffu, s, o);
    if (lane == 0) g_z[gw] = 1.0f / (s + 1e-6f);
}

// ---------------- launch ----------------
extern "C" void kernel_launch(void* const* d_in, const int* in_sizes, int n_in,
                              void* d_out, int out_size)
{
    const float* x      = (const float*)d_in[0];
    const float* qk_w   = (const float*)d_in[1];
    const float* qk_b   = (const float*)d_in[2];
    const float* lepe_w = (const float*)d_in[3];
    const float* lepe_b = (const float*)d_in[4];
    float* out = (float*)d_out;

    static cudaStream_t s1 = nullptr;
    static cudaEvent_t evX = nullptr, evL = nullptr;
    static int init_done = 0;
    if (!init_done) {
        cudaFuncSetAttribute(gemm_qk_cp, cudaFuncAttributeMaxDynamicSharedMemorySize, DSMEM_BYTES);
        cudaFuncSetAttribute(lepe_cp,    cudaFuncAttributeMaxDynamicSharedMemorySize, DSMEM_BYTES);
        cudaFuncSetAttribute(kv_cp,      cudaFuncAttributeMaxDynamicSharedMemorySize, KV_DSMEM);
        cudaFuncSetAttribute(out_cp,     cudaFuncAttributeMaxDynamicSharedMemorySize, DSMEM_BYTES);
        cudaStreamCreateWithFlags(&s1, cudaStreamNonBlocking);
        cudaEventCreateWithFlags(&evX, cudaEventDisableTiming);
        cudaEventCreateWithFlags(&evL, cudaEventDisableTiming);
        init_done = 1;
    }

    float* d_xt;     cudaGetSymbolAddress((void**)&d_xt,     g_xt);
    float* d_qkwC;   cudaGetSymbolAddress((void**)&d_qkwC,   g_qkwC);
    float* d_lepewC; cudaGetSymbolAddress((void**)&d_lepewC, g_lepewC);

    // stream 0: x conversion (needed by both branches)
    cvt_tf32_kernel<<<M_TOT * CC / 1024, 256>>>(x, d_xt);
    cudaEventRecord(evX, 0);

    // stream 1 (fork): lepe branch
    cudaStreamWaitEvent(s1, evX, 0);
    cvt_tf32_kernel<<<3 * CC * CC / 1024, 256, 0, s1>>>(lepe_w, d_lepewC);
    lepe_cp<<<dim3(8, 128), 256, DSMEM_BYTES, s1>>>();
    cudaEventRecord(evL, s1);

    // stream 0: attention chain
    theta_init_kernel<<<1, 512>>>();
    cvt_tf32_kernel<<<2 * CC * CC / 1024, 256>>>(qk_w, d_qkwC);
    gemm_qk_cp<<<dim3(16, 128), 256, DSMEM_BYTES>>>(qk_b);
    kmean_part_kernel<<<dim3(KM_CHUNKS, BB), 256>>>();
    kmean_fin_kernel<<<16, 256>>>();
    z_kernel<<<(BB * HH * NN * 32) / 256, 256>>>();
    kv_cp<<<dim3(KV_CHUNKS, BB * HH), 256, KV_DSMEM>>>();
    kv_reduce_kernel<<<(BB * HH * DD * DD) / 256, 256>>>();

    // join: out needs lepe result
    cudaStreamWaitEvent(0, evL, 0);
    out_cp<<<dim3(32, 32), 256, DSMEM_BYTES>>>(out, lepe_b);
}